// round 10
// baseline (speedup 1.0000x reference)
#include <cuda_runtime.h>
#include <cuda_fp16.h>
#include <cstdint>

#define NTX    100000
#define NUSER  20000
#define NMERCH 5000
#define NEDGE  400000
#define HDIM   256
#define HHALF  128
#define FIN    32

// ---------------------------------------------------------------------------
// Workspace (single __device__ global; no allocations allowed)
// ---------------------------------------------------------------------------
struct WS {
    float xt[2][NTX * HDIM];
    float gts[2][NTX * HDIM];
    float mm [NMERCH * HDIM];
    float mu [NUSER * HDIM];
    float yu [2][NUSER * HDIM];
    float ym [2][NMERCH * HDIM];
    float xu1[NUSER * HDIM];
    float xm1[NMERCH * HDIM];
    float bcat[HDIM];
    float w2cat[HDIM];
    // fp16 weights, transposed to [n][k]
    __half wp_h  [HDIM * FIN];
    __half wl0h[2][HDIM * HDIM];
    __half wl2h[2][HDIM * HDIM];
    __half wl1h  [HDIM * HDIM];
    __half wr1h  [HDIM * HDIM];
    __half wl3h  [HDIM * HDIM];
    __half wr3h  [HDIM * HDIM];
    __half wsum_h[2][HDIM * HDIM];
    __half wcat_h[HDIM * HDIM];
    int deg   [4][NTX];
    int cursor[4][NTX];
    int rowptr[4][NTX + 1];
    int perm  [4][NEDGE];
};
__device__ WS g_ws;

// relations: 0 = user->tx, 1 = tx->merch, 2 = merch->tx, 3 = tx->user
// ---------------------------------------------------------------------------
// CSR build
// ---------------------------------------------------------------------------
__global__ void build_count(const int* __restrict__ d0, const int* __restrict__ d1,
                            const int* __restrict__ d2, const int* __restrict__ d3) {
    int i = blockIdx.x * blockDim.x + threadIdx.x;
    if (i >= NEDGE) return;
    int rel = blockIdx.y;
    const int* d = (rel == 0) ? d0 : (rel == 1) ? d1 : (rel == 2) ? d2 : d3;
    atomicAdd(&g_ws.deg[rel][d[i]], 1);
}

__global__ void scan4(int n0, int n1, int n2, int n3) {
    int rel = blockIdx.x;
    int n = (rel == 0) ? n0 : (rel == 1) ? n1 : (rel == 2) ? n2 : n3;
    const int* deg = g_ws.deg[rel];
    int* rp = g_ws.rowptr[rel];
    __shared__ int wsum[32];
    __shared__ int s_carry;
    int tid = threadIdx.x, lane = tid & 31, wid = tid >> 5;
    if (tid == 0) s_carry = 0;
    __syncthreads();
    for (int base = 0; base < n; base += 1024) {
        int i = base + tid;
        int v = (i < n) ? deg[i] : 0;
        int x = v;
        #pragma unroll
        for (int off = 1; off < 32; off <<= 1) {
            int u = __shfl_up_sync(0xffffffffu, x, off);
            if (lane >= off) x += u;
        }
        if (lane == 31) wsum[wid] = x;
        __syncthreads();
        if (wid == 0) {
            int w = wsum[lane];
            int y = w;
            #pragma unroll
            for (int off = 1; off < 32; off <<= 1) {
                int u = __shfl_up_sync(0xffffffffu, y, off);
                if (lane >= off) y += u;
            }
            wsum[lane] = y - w;
        }
        __syncthreads();
        int incl = x + wsum[wid];
        int c = s_carry;
        __syncthreads();
        if (i < n) rp[i] = c + incl - v;
        if (tid == 1023) s_carry = c + incl;
        __syncthreads();
    }
    if (tid == 0) rp[n] = s_carry;
}

__global__ void build_fill(const int* __restrict__ s0, const int* __restrict__ d0,
                           const int* __restrict__ s1, const int* __restrict__ d1,
                           const int* __restrict__ s2, const int* __restrict__ d2,
                           const int* __restrict__ s3, const int* __restrict__ d3) {
    int i = blockIdx.x * blockDim.x + threadIdx.x;
    if (i >= NEDGE) return;
    int rel = blockIdx.y;
    const int* s = (rel == 0) ? s0 : (rel == 1) ? s1 : (rel == 2) ? s2 : s3;
    const int* d = (rel == 0) ? d0 : (rel == 1) ? d1 : (rel == 2) ? d2 : d3;
    int dst = d[i];
    int pos = g_ws.rowptr[rel][dst] + atomicAdd(&g_ws.cursor[rel][dst], 1);
    g_ws.perm[rel][pos] = s[i];
}

// ---------------------------------------------------------------------------
// Prep: batched fp16 transposed weight conversion (one launch for 9 matrices)
// ---------------------------------------------------------------------------
__global__ void conv_all(const float* __restrict__ Wl, const float* __restrict__ Wr,
                         const float* __restrict__ Wp) {
    int m = blockIdx.y;
    int i = blockIdx.x * blockDim.x + threadIdx.x;
    if (m == 0) {
        if (i >= HDIM * FIN) return;
        int n = i / FIN, k = i % FIN;
        g_ws.wp_h[i] = __float2half(Wp[k * HDIM + n]);
        return;
    }
    if (i >= HDIM * HDIM) return;
    const float* src;
    __half* dst;
    const size_t S = (size_t)HDIM * HDIM;
    switch (m) {
        case 1: src = Wl + 0 * S; dst = g_ws.wl0h[0]; break;
        case 2: src = Wl + 2 * S; dst = g_ws.wl2h[0]; break;
        case 3: src = Wl + 4 * S; dst = g_ws.wl0h[1]; break;
        case 4: src = Wl + 6 * S; dst = g_ws.wl2h[1]; break;
        case 5: src = Wl + 1 * S; dst = g_ws.wl1h;    break;
        case 6: src = Wr + 1 * S; dst = g_ws.wr1h;    break;
        case 7: src = Wl + 3 * S; dst = g_ws.wl3h;    break;
        default: src = Wr + 3 * S; dst = g_ws.wr3h;   break;
    }
    int n = i >> 8, k = i & 255;
    dst[i] = __float2half(src[k * HDIM + n]);
}

__global__ void prep_wsum_h(const float* __restrict__ Wr) {
    int i = blockIdx.x * blockDim.x + threadIdx.x;
    if (i >= HDIM * HDIM) return;
    int l = blockIdx.y;
    int n = i >> 8, k = i & 255;
    const float* Wr0 = Wr + ((size_t)(l * 4 + 0)) * HDIM * HDIM;
    const float* Wr2 = Wr + ((size_t)(l * 4 + 2)) * HDIM * HDIM;
    g_ws.wsum_h[l][i] = __float2half(Wr0[k * HDIM + n] + Wr2[k * HDIM + n]);
}

__global__ void prep_wcat_h(const float* __restrict__ Wc1, const float* __restrict__ Wv1,
                            const float* __restrict__ bc1, const float* __restrict__ bv1,
                            const float* __restrict__ Wc2, const float* __restrict__ Wv2) {
    int i = blockIdx.x * blockDim.x + threadIdx.x;
    if (i < HDIM * HDIM) {
        int n = i >> 8, k = i & 255;
        float v = (n < HHALF) ? Wc1[k * HHALF + n] : Wv1[k * HHALF + (n - HHALF)];
        g_ws.wcat_h[i] = __float2half(v);
    }
    if (i < HDIM) {
        g_ws.bcat[i]  = (i < HHALF) ? bc1[i] : bv1[i - HHALF];
        g_ws.w2cat[i] = (i < HHALF) ? Wc2[i] : Wv2[i - HHALF];
    }
}

// ---------------------------------------------------------------------------
// Segment-mean kernels
// ---------------------------------------------------------------------------
__global__ void seg_mean(const float* __restrict__ xsrc, int rel,
                         float* __restrict__ outm, int n_dst) {
    int w = (blockIdx.x * blockDim.x + threadIdx.x) >> 5;
    int lane = threadIdx.x & 31;
    if (w >= n_dst) return;
    const int* __restrict__ rp = g_ws.rowptr[rel];
    const int* __restrict__ pm = g_ws.perm[rel];
    int beg = rp[w], end = rp[w + 1];
    float4 a0 = make_float4(0.f, 0.f, 0.f, 0.f);
    float4 a1 = make_float4(0.f, 0.f, 0.f, 0.f);
    for (int e = beg; e < end; e++) {
        int s = pm[e];
        const float4* p = (const float4*)(xsrc + (size_t)s * HDIM);
        float4 v0 = p[lane];
        float4 v1 = p[lane + 32];
        a0.x += v0.x; a0.y += v0.y; a0.z += v0.z; a0.w += v0.w;
        a1.x += v1.x; a1.y += v1.y; a1.z += v1.z; a1.w += v1.w;
    }
    float inv = 1.0f / (float)max(end - beg, 1);
    a0.x *= inv; a0.y *= inv; a0.z *= inv; a0.w *= inv;
    a1.x *= inv; a1.y *= inv; a1.z *= inv; a1.w *= inv;
    float4* o = (float4*)(outm + (size_t)w * HDIM);
    o[lane] = a0;
    o[lane + 32] = a1;
}

__global__ void seg_mean_dual(const float* __restrict__ ya, const float* __restrict__ yb,
                              float* __restrict__ outm) {
    int w = (blockIdx.x * blockDim.x + threadIdx.x) >> 5;
    int lane = threadIdx.x & 31;
    if (w >= NTX) return;

    float4 r0 = make_float4(0.f, 0.f, 0.f, 0.f);
    float4 r1 = make_float4(0.f, 0.f, 0.f, 0.f);

    {
        const int* __restrict__ rp = g_ws.rowptr[0];
        const int* __restrict__ pm = g_ws.perm[0];
        int beg = rp[w], end = rp[w + 1];
        float4 a0 = make_float4(0.f, 0.f, 0.f, 0.f);
        float4 a1 = make_float4(0.f, 0.f, 0.f, 0.f);
        for (int e = beg; e < end; e++) {
            int s = pm[e];
            const float4* p = (const float4*)(ya + (size_t)s * HDIM);
            float4 v0 = p[lane];
            float4 v1 = p[lane + 32];
            a0.x += v0.x; a0.y += v0.y; a0.z += v0.z; a0.w += v0.w;
            a1.x += v1.x; a1.y += v1.y; a1.z += v1.z; a1.w += v1.w;
        }
        float inv = 1.0f / (float)max(end - beg, 1);
        r0.x += a0.x * inv; r0.y += a0.y * inv; r0.z += a0.z * inv; r0.w += a0.w * inv;
        r1.x += a1.x * inv; r1.y += a1.y * inv; r1.z += a1.z * inv; r1.w += a1.w * inv;
    }
    {
        const int* __restrict__ rp = g_ws.rowptr[2];
        const int* __restrict__ pm = g_ws.perm[2];
        int beg = rp[w], end = rp[w + 1];
        float4 a0 = make_float4(0.f, 0.f, 0.f, 0.f);
        float4 a1 = make_float4(0.f, 0.f, 0.f, 0.f);
        for (int e = beg; e < end; e++) {
            int s = pm[e];
            const float4* p = (const float4*)(yb + (size_t)s * HDIM);
            float4 v0 = p[lane];
            float4 v1 = p[lane + 32];
            a0.x += v0.x; a0.y += v0.y; a0.z += v0.z; a0.w += v0.w;
            a1.x += v1.x; a1.y += v1.y; a1.z += v1.z; a1.w += v1.w;
        }
        float inv = 1.0f / (float)max(end - beg, 1);
        r0.x += a0.x * inv; r0.y += a0.y * inv; r0.z += a0.z * inv; r0.w += a0.w * inv;
        r1.x += a1.x * inv; r1.y += a1.y * inv; r1.z += a1.z * inv; r1.w += a1.w * inv;
    }

    float4* o = (float4*)(outm + (size_t)w * HDIM);
    o[lane] = r0;
    o[lane + 32] = r1;
}

// ---------------------------------------------------------------------------
// Fused multi-segment GEMM: fp16 tensor cores (m16n8k16, fp32 acc),
// cp.async double-buffered. A fp32 [m][k] (cvt at fragment), W fp16 [n][k].
// ---------------------------------------------------------------------------
#define BM 128
#define BN 128
#define BK 32
#define AST 40
#define WPAD 56
#define A_STAGE_BYTES (BM * AST * 4)
#define W_STAGE_BYTES (BN * WPAD * 2)
#define STAGE_BYTES (A_STAGE_BYTES + W_STAGE_BYTES)
#define GEMM_SMEM_BYTES (2 * STAGE_BYTES)

struct GemmArgs {
    const float* A[4];
    const __half* W[4];
    const float* b0;
    const float* b1;
    const float* E0;
    float* C;
    int M, N, nseg, segK;
    float outscale;
    int relu;
    int headmode;
    const float* w2;
    const float* b2c;
    const float* b2v;
};

__device__ __forceinline__ uint32_t packh2(float x, float y) {
    __half2 h = __floats2half2_rn(x, y);
    return *(uint32_t*)&h;
}

__device__ __forceinline__ void cp_async16(uint32_t smem_addr, const void* gptr, int src_bytes) {
    asm volatile("cp.async.cg.shared.global [%0], [%1], 16, %2;"
                 :: "r"(smem_addr), "l"(gptr), "r"(src_bytes));
}
__device__ __forceinline__ void cp_commit() {
    asm volatile("cp.async.commit_group;");
}
template <int N>
__device__ __forceinline__ void cp_wait() {
    asm volatile("cp.async.wait_group %0;" :: "n"(N));
}

__global__ void __launch_bounds__(256, 2) gemm_fp16(GemmArgs g) {
    extern __shared__ char smem_c[];

    int tid = threadIdx.x;
    int lane = tid & 31;
    int warp = tid >> 5;
    int wm = (warp & 3) * 32;
    int wn = (warp >> 2) * 64;
    int grp = lane >> 2;
    int tg  = lane & 3;

    int m0 = blockIdx.x * BM, n0 = blockIdx.y * BN;

    int ld_row = tid >> 1;
    int a_cb = (tid & 1) * 4;
    int w_cb = (tid & 1) * 2;

    int a_grow = m0 + ld_row;
    bool a_ok = (a_grow < g.M);

    uint32_t smem_base = (uint32_t)__cvta_generic_to_shared(smem_c);
    int ktiles = g.nseg * g.segK / BK;

    auto issue_tile = [&](int kt, int st) {
        int k0 = kt * BK;
        int seg = k0 / g.segK;
        int koff = k0 - seg * g.segK;
        const float* A = g.A[seg];
        const __half* W = g.W[seg];

        uint32_t a_s = smem_base + st * STAGE_BYTES + ld_row * (AST * 4);
        const float* a_g = A + (size_t)a_grow * g.segK + koff;
        int a_sz = a_ok ? 16 : 0;
        #pragma unroll
        for (int c = 0; c < 4; c++)
            cp_async16(a_s + (a_cb + c) * 16, a_g + (a_cb + c) * 4, a_sz);

        uint32_t w_s = smem_base + st * STAGE_BYTES + A_STAGE_BYTES + ld_row * (WPAD * 2);
        const __half* w_g = W + (size_t)(n0 + ld_row) * g.segK + koff;
        #pragma unroll
        for (int c = 0; c < 2; c++)
            cp_async16(w_s + (w_cb + c) * 16, w_g + (w_cb + c) * 8, 16);

        cp_commit();
    };

    float acc[2][8][4];
    #pragma unroll
    for (int i = 0; i < 2; i++)
        #pragma unroll
        for (int j = 0; j < 8; j++)
            #pragma unroll
            for (int c = 0; c < 4; c++) acc[i][j][c] = 0.f;

    issue_tile(0, 0);

    for (int kt = 0; kt < ktiles; kt++) {
        int st = kt & 1;
        if (kt + 1 < ktiles) {
            issue_tile(kt + 1, (kt + 1) & 1);
            cp_wait<1>();
        } else {
            cp_wait<0>();
        }
        __syncthreads();

        const float* As = (const float*)(smem_c + st * STAGE_BYTES);
        const __half* Ws = (const __half*)(smem_c + st * STAGE_BYTES + A_STAGE_BYTES);

        #pragma unroll
        for (int ks = 0; ks < BK / 16; ks++) {
            int kb = ks * 16;
            uint32_t afr[2][4];
            #pragma unroll
            for (int mi = 0; mi < 2; mi++) {
                int r = wm + mi * 16 + grp;
                float2 f00 = *(const float2*)(As + r * AST + kb + 2 * tg);
                float2 f10 = *(const float2*)(As + (r + 8) * AST + kb + 2 * tg);
                float2 f01 = *(const float2*)(As + r * AST + kb + 8 + 2 * tg);
                float2 f11 = *(const float2*)(As + (r + 8) * AST + kb + 8 + 2 * tg);
                afr[mi][0] = packh2(f00.x, f00.y);
                afr[mi][1] = packh2(f10.x, f10.y);
                afr[mi][2] = packh2(f01.x, f01.y);
                afr[mi][3] = packh2(f11.x, f11.y);
            }
            uint32_t bfr[8][2];
            #pragma unroll
            for (int nt = 0; nt < 8; nt++) {
                int nb = wn + nt * 8 + grp;
                bfr[nt][0] = *(const uint32_t*)(Ws + nb * WPAD + kb + 2 * tg);
                bfr[nt][1] = *(const uint32_t*)(Ws + nb * WPAD + kb + 8 + 2 * tg);
            }
            #pragma unroll
            for (int mi = 0; mi < 2; mi++) {
                #pragma unroll
                for (int nt = 0; nt < 8; nt++) {
                    asm volatile(
                        "mma.sync.aligned.m16n8k16.row.col.f32.f16.f16.f32 "
                        "{%0,%1,%2,%3}, {%4,%5,%6,%7}, {%8,%9}, {%0,%1,%2,%3};"
                        : "+f"(acc[mi][nt][0]), "+f"(acc[mi][nt][1]),
                          "+f"(acc[mi][nt][2]), "+f"(acc[mi][nt][3])
                        : "r"(afr[mi][0]), "r"(afr[mi][1]),
                          "r"(afr[mi][2]), "r"(afr[mi][3]),
                          "r"(bfr[nt][0]), "r"(bfr[nt][1]));
                }
            }
        }
        __syncthreads();
    }

    float bias[8][2];
    #pragma unroll
    for (int nt = 0; nt < 8; nt++) {
        int c = n0 + wn + nt * 8 + tg * 2;
        float b0v = 0.f, b1v = 0.f;
        if (g.b0) { b0v = g.b0[c] + (g.b1 ? g.b1[c] : 0.f); }
        if (g.b0) { b1v = g.b0[c + 1] + (g.b1 ? g.b1[c + 1] : 0.f); }
        bias[nt][0] = b0v;
        bias[nt][1] = b1v;
    }

    if (g.headmode) {
        float* red = (float*)smem_c;
        for (int i = tid; i < BM; i += 256) red[i] = 0.f;
        __syncthreads();
        #pragma unroll
        for (int mi = 0; mi < 2; mi++) {
            float p0 = 0.f, p1 = 0.f;
            #pragma unroll
            for (int nt = 0; nt < 8; nt++) {
                int c = n0 + wn + nt * 8 + tg * 2;
                float w20 = g.w2[c], w21 = g.w2[c + 1];
                float v00 = fmaxf(acc[mi][nt][0] + bias[nt][0], 0.f);
                float v01 = fmaxf(acc[mi][nt][1] + bias[nt][1], 0.f);
                float v10 = fmaxf(acc[mi][nt][2] + bias[nt][0], 0.f);
                float v11 = fmaxf(acc[mi][nt][3] + bias[nt][1], 0.f);
                p0 += v00 * w20 + v01 * w21;
                p1 += v10 * w20 + v11 * w21;
            }
            atomicAdd(&red[wm + mi * 16 + grp], p0);
            atomicAdd(&red[wm + mi * 16 + grp + 8], p1);
        }
        __syncthreads();
        if (tid < BM) {
            int row = m0 + tid;
            if (row < g.M) {
                int off = (n0 >= HHALF) ? NTX : 0;
                float b2 = (n0 >= HHALF) ? g.b2v[0] : g.b2c[0];
                g.C[off + row] = red[tid] + b2;
            }
        }
        return;
    }

    #pragma unroll
    for (int mi = 0; mi < 2; mi++) {
        int r0 = m0 + wm + mi * 16 + grp;
        int r1 = r0 + 8;
        #pragma unroll
        for (int nt = 0; nt < 8; nt++) {
            int c = n0 + wn + nt * 8 + tg * 2;
            if (r0 < g.M) {
                float e0 = 0.f, e1 = 0.f;
                if (g.E0) {
                    float2 t = *(const float2*)(g.E0 + (size_t)r0 * g.N + c);
                    e0 += t.x; e1 += t.y;
                }
                float v0 = (acc[mi][nt][0] + bias[nt][0] + e0) * g.outscale;
                float v1 = (acc[mi][nt][1] + bias[nt][1] + e1) * g.outscale;
                if (g.relu) { v0 = fmaxf(v0, 0.f); v1 = fmaxf(v1, 0.f); }
                *(float2*)(g.C + (size_t)r0 * g.N + c) = make_float2(v0, v1);
            }
            if (r1 < g.M) {
                float e0 = 0.f, e1 = 0.f;
                if (g.E0) {
                    float2 t = *(const float2*)(g.E0 + (size_t)r1 * g.N + c);
                    e0 += t.x; e1 += t.y;
                }
                float v0 = (acc[mi][nt][2] + bias[nt][0] + e0) * g.outscale;
                float v1 = (acc[mi][nt][3] + bias[nt][1] + e1) * g.outscale;
                if (g.relu) { v0 = fmaxf(v0, 0.f); v1 = fmaxf(v1, 0.f); }
                *(float2*)(g.C + (size_t)r1 * g.N + c) = make_float2(v0, v1);
            }
        }
    }
}

// ---------------------------------------------------------------------------
// Host orchestration: gather-first 3-stream schedule
// ---------------------------------------------------------------------------
static inline int ceil_div(int a, int b) { return (a + b - 1) / b; }

extern "C" void kernel_launch(void* const* d_in, const int* in_sizes, int n_in,
                              void* d_out, int out_size) {
    const float* x_tx   = (const float*)d_in[0];
    const float* x_user = (const float*)d_in[1];
    const float* x_merch= (const float*)d_in[2];
    const float* Wp     = (const float*)d_in[3];
    const float* bp     = (const float*)d_in[4];
    const float* Wl     = (const float*)d_in[5];
    const float* bl     = (const float*)d_in[6];
    const float* Wr     = (const float*)d_in[7];
    const float* Wc1    = (const float*)d_in[8];
    const float* bc1    = (const float*)d_in[9];
    const float* Wc2    = (const float*)d_in[10];
    const float* bc2    = (const float*)d_in[11];
    const float* Wv1    = (const float*)d_in[12];
    const float* bv1    = (const float*)d_in[13];
    const float* Wv2    = (const float*)d_in[14];
    const float* bv2    = (const float*)d_in[15];
    const int* e_ut_src = (const int*)d_in[16];
    const int* e_ut_dst = (const int*)d_in[17];
    const int* e_tm_src = (const int*)d_in[18];
    const int* e_tm_dst = (const int*)d_in[19];
    const int* e_mt_src = (const int*)d_in[20];
    const int* e_mt_dst = (const int*)d_in[21];
    const int* e_tu_src = (const int*)d_in[22];
    const int* e_tu_dst = (const int*)d_in[23];
    float* out = (float*)d_out;

    WS* ws = nullptr;
    cudaGetSymbolAddress((void**)&ws, g_ws);

    static cudaStream_t sB = nullptr, sC = nullptr;
    static cudaEvent_t ev[10];
    if (!sB) {
        cudaStreamCreateWithFlags(&sB, cudaStreamNonBlocking);
        cudaStreamCreateWithFlags(&sC, cudaStreamNonBlocking);
        for (int i = 0; i < 10; i++)
            cudaEventCreateWithFlags(&ev[i], cudaEventDisableTiming);
        cudaFuncSetAttribute(gemm_fp16, cudaFuncAttributeMaxDynamicSharedMemorySize,
                             GEMM_SMEM_BYTES);
    }
    cudaStream_t s0 = 0;
    cudaEvent_t evFork0 = ev[0], evPrep = ev[1], evCsr = ev[2], evProj = ev[3];
    cudaEvent_t evY0 = ev[4], evGts0 = ev[5], evYm1 = ev[6], evGts1 = ev[7];

    const float* bl0_0 = bl + 0 * HDIM;
    const float* bl1_0 = bl + 1 * HDIM;
    const float* bl2_0 = bl + 2 * HDIM;
    const float* bl3_0 = bl + 3 * HDIM;
    const float* bl0_1 = bl + 4 * HDIM;
    const float* bl2_1 = bl + 6 * HDIM;

    cudaEventRecord(evFork0, s0);
    cudaStreamWaitEvent(sB, evFork0, 0);
    cudaStreamWaitEvent(sC, evFork0, 0);

    // ======== sC: batched prep -> yu0/ym0 -> (proj) mu0 -> xu1 -> yu1 -> dual1 ========
    int cg = ceil_div(HDIM * HDIM, 256);
    conv_all<<<dim3(cg, 9), 256, 0, sC>>>(Wl, Wr, Wp);
    prep_wsum_h<<<dim3(cg, 2), 256, 0, sC>>>(Wr);
    prep_wcat_h<<<cg, 256, 0, sC>>>(Wc1, Wv1, bc1, bv1, Wc2, Wv2);
    cudaEventRecord(evPrep, sC);
    {
        GemmArgs a = {};
        a.A[0] = x_user; a.W[0] = ws->wl0h[0];
        a.C = ws->yu[0]; a.M = NUSER; a.N = HDIM; a.nseg = 1; a.segK = HDIM;
        a.outscale = 1.0f; a.relu = 0;
        gemm_fp16<<<dim3(ceil_div(NUSER, BM), HDIM / BN), 256, GEMM_SMEM_BYTES, sC>>>(a);
    }
    {
        GemmArgs a = {};
        a.A[0] = x_merch; a.W[0] = ws->wl2h[0];
        a.C = ws->ym[0]; a.M = NMERCH; a.N = HDIM; a.nseg = 1; a.segK = HDIM;
        a.outscale = 1.0f; a.relu = 0;
        gemm_fp16<<<dim3(ceil_div(NMERCH, BM), HDIM / BN), 256, GEMM_SMEM_BYTES, sC>>>(a);
    }
    cudaEventRecord(evY0, sC);

    // ======== sB: CSR build -> dual0 ========
    cudaMemsetAsync(ws->deg,    0, sizeof(ws->deg),    sB);
    cudaMemsetAsync(ws->cursor, 0, sizeof(ws->cursor), sB);
    build_count<<<dim3(ceil_div(NEDGE, 256), 4), 256, 0, sB>>>(e_ut_dst, e_tm_dst, e_mt_dst, e_tu_dst);
    scan4<<<4, 1024, 0, sB>>>(NTX, NMERCH, NTX, NUSER);
    build_fill<<<dim3(ceil_div(NEDGE, 256), 4), 256, 0, sB>>>(e_ut_src, e_ut_dst, e_tm_src, e_tm_dst,
                                                              e_mt_src, e_mt_dst, e_tu_src, e_tu_dst);
    cudaEventRecord(evCsr, sB);
    cudaStreamWaitEvent(sB, evY0, 0);
    seg_mean_dual<<<ceil_div(NTX * 32, 256), 256, 0, sB>>>(ws->yu[0], ws->ym[0], ws->gts[0]);
    cudaEventRecord(evGts0, sB);

    // ======== s0: proj -> mm0 -> xm1 -> ym1 -> xtL0 -> xtL1 -> head ========
    cudaStreamWaitEvent(s0, evPrep, 0);
    {
        GemmArgs a = {};
        a.A[0] = x_tx; a.W[0] = ws->wp_h; a.b0 = bp;
        a.C = ws->xt[0]; a.M = NTX; a.N = HDIM; a.nseg = 1; a.segK = FIN;
        a.outscale = 1.0f; a.relu = 0;
        gemm_fp16<<<dim3(ceil_div(NTX, BM), HDIM / BN), 256, GEMM_SMEM_BYTES, s0>>>(a);
    }
    cudaEventRecord(evProj, s0);
    cudaStreamWaitEvent(s0, evCsr, 0);
    seg_mean<<<ceil_div(NMERCH * 32, 256), 256, 0, s0>>>(ws->xt[0], 1, ws->mm, NMERCH);
    {
        GemmArgs a = {};
        a.A[0] = ws->mm;  a.W[0] = ws->wl1h;
        a.A[1] = x_merch; a.W[1] = ws->wr1h;
        a.b0 = bl1_0;
        a.C = ws->xm1; a.M = NMERCH; a.N = HDIM; a.nseg = 2; a.segK = HDIM;
        a.outscale = 1.0f; a.relu = 1;
        gemm_fp16<<<dim3(ceil_div(NMERCH, BM), HDIM / BN), 256, GEMM_SMEM_BYTES, s0>>>(a);
    }
    {
        GemmArgs a = {};
        a.A[0] = ws->xm1; a.W[0] = ws->wl2h[1];
        a.C = ws->ym[1]; a.M = NMERCH; a.N = HDIM; a.nseg = 1; a.segK = HDIM;
        a.outscale = 1.0f; a.relu = 0;
        gemm_fp16<<<dim3(ceil_div(NMERCH, BM), HDIM / BN), 256, GEMM_SMEM_BYTES, s0>>>(a);
    }
    cudaEventRecord(evYm1, s0);

    // ======== sC (cont): mu0 -> xu1 -> yu1 -> dual1 ========
    cudaStreamWaitEvent(sC, evCsr, 0);
    cudaStreamWaitEvent(sC, evProj, 0);
    seg_mean<<<ceil_div(NUSER * 32, 256), 256, 0, sC>>>(ws->xt[0], 3, ws->mu, NUSER);
    {
        GemmArgs a = {};
        a.A[0] = ws->mu; a.W[0] = ws->wl3h;
        a.A[1] = x_user; a.W[1] = ws->wr3h;
        a.b0 = bl3_0;
        a.C = ws->xu1; a.M = NUSER; a.N = HDIM; a.nseg = 2; a.segK = HDIM;
        a.outscale = 1.0f; a.relu = 1;
        gemm_fp16<<<dim3(ceil_div(NUSER, BM), HDIM / BN), 256, GEMM_SMEM_BYTES, sC>>>(a);
    }
    {
        GemmArgs a = {};
        a.A[0] = ws->xu1; a.W[0] = ws->wl0h[1];
        a.C = ws->yu[1]; a.M = NUSER; a.N = HDIM; a.nseg = 1; a.segK = HDIM;
        a.outscale = 1.0f; a.relu = 0;
        gemm_fp16<<<dim3(ceil_div(NUSER, BM), HDIM / BN), 256, GEMM_SMEM_BYTES, sC>>>(a);
    }
    cudaStreamWaitEvent(sC, evYm1, 0);
    seg_mean_dual<<<ceil_div(NTX * 32, 256), 256, 0, sC>>>(ws->yu[1], ws->ym[1], ws->gts[1]);
    cudaEventRecord(evGts1, sC);

    // ======== s0 (cont): xtL0 -> xtL1 -> fused head ========
    cudaStreamWaitEvent(s0, evGts0, 0);
    {
        GemmArgs a = {};
        a.A[0] = ws->xt[0]; a.W[0] = ws->wsum_h[0];
        a.b0 = bl0_0; a.b1 = bl2_0;
        a.E0 = ws->gts[0];
        a.C = ws->xt[1]; a.M = NTX; a.N = HDIM; a.nseg = 1; a.segK = HDIM;
        a.outscale = 0.5f; a.relu = 1;
        gemm_fp16<<<dim3(ceil_div(NTX, BM), HDIM / BN), 256, GEMM_SMEM_BYTES, s0>>>(a);
    }
    cudaStreamWaitEvent(s0, evGts1, 0);
    {
        GemmArgs a = {};
        a.A[0] = ws->xt[1]; a.W[0] = ws->wsum_h[1];
        a.b0 = bl0_1; a.b1 = bl2_1;
        a.E0 = ws->gts[1];
        a.C = ws->xt[0]; a.M = NTX; a.N = HDIM; a.nseg = 1; a.segK = HDIM;
        a.outscale = 0.5f; a.relu = 1;
        gemm_fp16<<<dim3(ceil_div(NTX, BM), HDIM / BN), 256, GEMM_SMEM_BYTES, s0>>>(a);
    }
    {
        GemmArgs a = {};
        a.A[0] = ws->xt[0]; a.W[0] = ws->wcat_h; a.b0 = ws->bcat;
        a.C = out; a.M = NTX; a.N = HDIM; a.nseg = 1; a.segK = HDIM;
        a.outscale = 1.0f; a.relu = 1;
        a.headmode = 1; a.w2 = ws->w2cat; a.b2c = bc2; a.b2v = bv2;
        gemm_fp16<<<dim3(ceil_div(NTX, BM), HDIM / BN), 256, GEMM_SMEM_BYTES, s0>>>(a);
    }
}

// round 11
// speedup vs baseline: 1.1498x; 1.1498x over previous
#include <cuda_runtime.h>
#include <cuda_fp16.h>
#include <cstdint>

#define NTX    100000
#define NUSER  20000
#define NMERCH 5000
#define NEDGE  400000
#define HDIM   256
#define HHALF  128
#define FIN    32

// ---------------------------------------------------------------------------
// Workspace (single __device__ global; no allocations allowed)
// ---------------------------------------------------------------------------
struct WS {
    // fp16 activations (GEMM-A-path; rounding identical to fragment cvt)
    __half xth[2][NTX * HDIM];      // xt after proj / xtL0 / xtL1
    __half xtx_h [NTX * FIN];       // x_tx as fp16
    __half xu_h  [NUSER * HDIM];    // x_user as fp16
    __half xm_h  [NMERCH * HDIM];   // x_merch as fp16
    __half mmh [NMERCH * HDIM];     // seg-mean -> merch (half)
    __half muh [NUSER * HDIM];      // seg-mean -> user (half)
    __half xm1h[NMERCH * HDIM];
    __half xu1h[NUSER * HDIM];
    // fp32 (feeds fp32 epilogue adds — precision-critical)
    float gts[2][NTX * HDIM];
    float yu [2][NUSER * HDIM];
    float ym [2][NMERCH * HDIM];
    float bcat[HDIM];
    float w2cat[HDIM];
    // fp16 weights, transposed to [n][k]
    __half wp_h  [HDIM * FIN];
    __half wl0h[2][HDIM * HDIM];
    __half wl2h[2][HDIM * HDIM];
    __half wl1h  [HDIM * HDIM];
    __half wr1h  [HDIM * HDIM];
    __half wl3h  [HDIM * HDIM];
    __half wr3h  [HDIM * HDIM];
    __half wsum_h[2][HDIM * HDIM];
    __half wcat_h[HDIM * HDIM];
    int deg   [4][NTX];
    int cursor[4][NTX];
    int rowptr[4][NTX + 1];
    int perm  [4][NEDGE];
};
__device__ WS g_ws;

// relations: 0 = user->tx, 1 = tx->merch, 2 = merch->tx, 3 = tx->user
// ---------------------------------------------------------------------------
// CSR build
// ---------------------------------------------------------------------------
__global__ void build_count(const int* __restrict__ d0, const int* __restrict__ d1,
                            const int* __restrict__ d2, const int* __restrict__ d3) {
    int i = blockIdx.x * blockDim.x + threadIdx.x;
    if (i >= NEDGE) return;
    int rel = blockIdx.y;
    const int* d = (rel == 0) ? d0 : (rel == 1) ? d1 : (rel == 2) ? d2 : d3;
    atomicAdd(&g_ws.deg[rel][d[i]], 1);
}

__global__ void scan4(int n0, int n1, int n2, int n3) {
    int rel = blockIdx.x;
    int n = (rel == 0) ? n0 : (rel == 1) ? n1 : (rel == 2) ? n2 : n3;
    const int* deg = g_ws.deg[rel];
    int* rp = g_ws.rowptr[rel];
    __shared__ int wsum[32];
    __shared__ int s_carry;
    int tid = threadIdx.x, lane = tid & 31, wid = tid >> 5;
    if (tid == 0) s_carry = 0;
    __syncthreads();
    for (int base = 0; base < n; base += 1024) {
        int i = base + tid;
        int v = (i < n) ? deg[i] : 0;
        int x = v;
        #pragma unroll
        for (int off = 1; off < 32; off <<= 1) {
            int u = __shfl_up_sync(0xffffffffu, x, off);
            if (lane >= off) x += u;
        }
        if (lane == 31) wsum[wid] = x;
        __syncthreads();
        if (wid == 0) {
            int w = wsum[lane];
            int y = w;
            #pragma unroll
            for (int off = 1; off < 32; off <<= 1) {
                int u = __shfl_up_sync(0xffffffffu, y, off);
                if (lane >= off) y += u;
            }
            wsum[lane] = y - w;
        }
        __syncthreads();
        int incl = x + wsum[wid];
        int c = s_carry;
        __syncthreads();
        if (i < n) rp[i] = c + incl - v;
        if (tid == 1023) s_carry = c + incl;
        __syncthreads();
    }
    if (tid == 0) rp[n] = s_carry;
}

__global__ void build_fill(const int* __restrict__ s0, const int* __restrict__ d0,
                           const int* __restrict__ s1, const int* __restrict__ d1,
                           const int* __restrict__ s2, const int* __restrict__ d2,
                           const int* __restrict__ s3, const int* __restrict__ d3) {
    int i = blockIdx.x * blockDim.x + threadIdx.x;
    if (i >= NEDGE) return;
    int rel = blockIdx.y;
    const int* s = (rel == 0) ? s0 : (rel == 1) ? s1 : (rel == 2) ? s2 : s3;
    const int* d = (rel == 0) ? d0 : (rel == 1) ? d1 : (rel == 2) ? d2 : d3;
    int dst = d[i];
    int pos = g_ws.rowptr[rel][dst] + atomicAdd(&g_ws.cursor[rel][dst], 1);
    g_ws.perm[rel][pos] = s[i];
}

// ---------------------------------------------------------------------------
// Prep: batched fp16 transposed weight conversion + activation fp16 copies
// ---------------------------------------------------------------------------
__global__ void conv_all(const float* __restrict__ Wl, const float* __restrict__ Wr,
                         const float* __restrict__ Wp) {
    int m = blockIdx.y;
    int i = blockIdx.x * blockDim.x + threadIdx.x;
    if (m == 0) {
        if (i >= HDIM * FIN) return;
        int n = i / FIN, k = i % FIN;
        g_ws.wp_h[i] = __float2half(Wp[k * HDIM + n]);
        return;
    }
    if (i >= HDIM * HDIM) return;
    const float* src;
    __half* dst;
    const size_t S = (size_t)HDIM * HDIM;
    switch (m) {
        case 1: src = Wl + 0 * S; dst = g_ws.wl0h[0]; break;
        case 2: src = Wl + 2 * S; dst = g_ws.wl2h[0]; break;
        case 3: src = Wl + 4 * S; dst = g_ws.wl0h[1]; break;
        case 4: src = Wl + 6 * S; dst = g_ws.wl2h[1]; break;
        case 5: src = Wl + 1 * S; dst = g_ws.wl1h;    break;
        case 6: src = Wr + 1 * S; dst = g_ws.wr1h;    break;
        case 7: src = Wl + 3 * S; dst = g_ws.wl3h;    break;
        default: src = Wr + 3 * S; dst = g_ws.wr3h;   break;
    }
    int n = i >> 8, k = i & 255;
    dst[i] = __float2half(src[k * HDIM + n]);
}

__global__ void prep_wsum_h(const float* __restrict__ Wr) {
    int i = blockIdx.x * blockDim.x + threadIdx.x;
    if (i >= HDIM * HDIM) return;
    int l = blockIdx.y;
    int n = i >> 8, k = i & 255;
    const float* Wr0 = Wr + ((size_t)(l * 4 + 0)) * HDIM * HDIM;
    const float* Wr2 = Wr + ((size_t)(l * 4 + 2)) * HDIM * HDIM;
    g_ws.wsum_h[l][i] = __float2half(Wr0[k * HDIM + n] + Wr2[k * HDIM + n]);
}

__global__ void prep_wcat_h(const float* __restrict__ Wc1, const float* __restrict__ Wv1,
                            const float* __restrict__ bc1, const float* __restrict__ bv1,
                            const float* __restrict__ Wc2, const float* __restrict__ Wv2) {
    int i = blockIdx.x * blockDim.x + threadIdx.x;
    if (i < HDIM * HDIM) {
        int n = i >> 8, k = i & 255;
        float v = (n < HHALF) ? Wc1[k * HHALF + n] : Wv1[k * HHALF + (n - HHALF)];
        g_ws.wcat_h[i] = __float2half(v);
    }
    if (i < HDIM) {
        g_ws.bcat[i]  = (i < HHALF) ? bc1[i] : bv1[i - HHALF];
        g_ws.w2cat[i] = (i < HHALF) ? Wc2[i] : Wv2[i - HHALF];
    }
}

// float -> half elementwise (4 per thread)
__global__ void conv_x(const float* __restrict__ x, __half* __restrict__ y, int n4) {
    int i = blockIdx.x * blockDim.x + threadIdx.x;
    if (i >= n4) return;
    float4 v = ((const float4*)x)[i];
    __half2 h0 = __floats2half2_rn(v.x, v.y);
    __half2 h1 = __floats2half2_rn(v.z, v.w);
    ((__half2*)y)[i * 2 + 0] = h0;
    ((__half2*)y)[i * 2 + 1] = h1;
}

// ---------------------------------------------------------------------------
// Segment-mean kernels
// ---------------------------------------------------------------------------
// half in -> half out (fp32 accumulation)
__global__ void seg_mean_h(const __half* __restrict__ xsrc, int rel,
                           __half* __restrict__ outm, int n_dst) {
    int w = (blockIdx.x * blockDim.x + threadIdx.x) >> 5;
    int lane = threadIdx.x & 31;
    if (w >= n_dst) return;
    const int* __restrict__ rp = g_ws.rowptr[rel];
    const int* __restrict__ pm = g_ws.perm[rel];
    int beg = rp[w], end = rp[w + 1];
    float acc[8];
    #pragma unroll
    for (int j = 0; j < 8; j++) acc[j] = 0.f;
    for (int e = beg; e < end; e++) {
        int s = pm[e];
        uint4 v = ((const uint4*)(xsrc + (size_t)s * HDIM))[lane];
        const __half2* h = (const __half2*)&v;
        #pragma unroll
        for (int j = 0; j < 4; j++) {
            float2 f = __half22float2(h[j]);
            acc[j * 2 + 0] += f.x;
            acc[j * 2 + 1] += f.y;
        }
    }
    float inv = 1.0f / (float)max(end - beg, 1);
    uint4 o;
    __half2* oh = (__half2*)&o;
    #pragma unroll
    for (int j = 0; j < 4; j++)
        oh[j] = __floats2half2_rn(acc[j * 2] * inv, acc[j * 2 + 1] * inv);
    ((uint4*)(outm + (size_t)w * HDIM))[lane] = o;
}

// fp32 dual gather: gts = mean_rel0(ya) + mean_rel2(yb)
__global__ void seg_mean_dual(const float* __restrict__ ya, const float* __restrict__ yb,
                              float* __restrict__ outm) {
    int w = (blockIdx.x * blockDim.x + threadIdx.x) >> 5;
    int lane = threadIdx.x & 31;
    if (w >= NTX) return;

    float4 r0 = make_float4(0.f, 0.f, 0.f, 0.f);
    float4 r1 = make_float4(0.f, 0.f, 0.f, 0.f);

    {
        const int* __restrict__ rp = g_ws.rowptr[0];
        const int* __restrict__ pm = g_ws.perm[0];
        int beg = rp[w], end = rp[w + 1];
        float4 a0 = make_float4(0.f, 0.f, 0.f, 0.f);
        float4 a1 = make_float4(0.f, 0.f, 0.f, 0.f);
        for (int e = beg; e < end; e++) {
            int s = pm[e];
            const float4* p = (const float4*)(ya + (size_t)s * HDIM);
            float4 v0 = p[lane];
            float4 v1 = p[lane + 32];
            a0.x += v0.x; a0.y += v0.y; a0.z += v0.z; a0.w += v0.w;
            a1.x += v1.x; a1.y += v1.y; a1.z += v1.z; a1.w += v1.w;
        }
        float inv = 1.0f / (float)max(end - beg, 1);
        r0.x += a0.x * inv; r0.y += a0.y * inv; r0.z += a0.z * inv; r0.w += a0.w * inv;
        r1.x += a1.x * inv; r1.y += a1.y * inv; r1.z += a1.z * inv; r1.w += a1.w * inv;
    }
    {
        const int* __restrict__ rp = g_ws.rowptr[2];
        const int* __restrict__ pm = g_ws.perm[2];
        int beg = rp[w], end = rp[w + 1];
        float4 a0 = make_float4(0.f, 0.f, 0.f, 0.f);
        float4 a1 = make_float4(0.f, 0.f, 0.f, 0.f);
        for (int e = beg; e < end; e++) {
            int s = pm[e];
            const float4* p = (const float4*)(yb + (size_t)s * HDIM);
            float4 v0 = p[lane];
            float4 v1 = p[lane + 32];
            a0.x += v0.x; a0.y += v0.y; a0.z += v0.z; a0.w += v0.w;
            a1.x += v1.x; a1.y += v1.y; a1.z += v1.z; a1.w += v1.w;
        }
        float inv = 1.0f / (float)max(end - beg, 1);
        r0.x += a0.x * inv; r0.y += a0.y * inv; r0.z += a0.z * inv; r0.w += a0.w * inv;
        r1.x += a1.x * inv; r1.y += a1.y * inv; r1.z += a1.z * inv; r1.w += a1.w * inv;
    }

    float4* o = (float4*)(outm + (size_t)w * HDIM);
    o[lane] = r0;
    o[lane + 32] = r1;
}

// ---------------------------------------------------------------------------
// Fused GEMM: fp16 A (smem half, direct half2 fragments), fp16 W [n][k],
// fp32 accumulate, cp.async double-buffered. Output fp32 or fp16, optional
// fp32 E0 epilogue add, optional fused head.
// ---------------------------------------------------------------------------
#define BM 128
#define BN 128
#define BK 32
#define ASTH 40                       // A smem stride in halves (80B)
#define WPAD 56                       // W smem stride in halves (112B)
#define A_STAGE_BYTES (BM * ASTH * 2)     // 10240
#define W_STAGE_BYTES (BN * WPAD * 2)     // 14336
#define STAGE_BYTES (A_STAGE_BYTES + W_STAGE_BYTES)  // 24576
#define GEMM_SMEM_BYTES (2 * STAGE_BYTES)            // 49152

struct GemmArgs {
    const __half* A[2];
    const __half* W[2];
    const float* b0;
    const float* b1;
    const float* E0;
    void* C;
    int M, N, nseg, segK;
    float outscale;
    int relu;
    int out_half;
    int headmode;
    const float* w2;
    const float* b2c;
    const float* b2v;
};

__device__ __forceinline__ void cp_async16(uint32_t smem_addr, const void* gptr, int src_bytes) {
    asm volatile("cp.async.cg.shared.global [%0], [%1], 16, %2;"
                 :: "r"(smem_addr), "l"(gptr), "r"(src_bytes));
}
__device__ __forceinline__ void cp_commit() {
    asm volatile("cp.async.commit_group;");
}
template <int N>
__device__ __forceinline__ void cp_wait() {
    asm volatile("cp.async.wait_group %0;" :: "n"(N));
}

__global__ void __launch_bounds__(256, 2) gemm_fp16(GemmArgs g) {
    extern __shared__ char smem_c[];

    int tid = threadIdx.x;
    int lane = tid & 31;
    int warp = tid >> 5;
    int wm = (warp & 3) * 32;
    int wn = (warp >> 2) * 64;
    int grp = lane >> 2;
    int tg  = lane & 3;

    int m0 = blockIdx.x * BM, n0 = blockIdx.y * BN;

    int ld_row = tid >> 1;          // 0..127 for both A and W rows
    int cb = (tid & 1) * 2;         // 2 chunks of 16B per thread (row = 64B)

    int a_grow = m0 + ld_row;
    bool a_ok = (a_grow < g.M);

    uint32_t smem_base = (uint32_t)__cvta_generic_to_shared(smem_c);
    int ktiles = g.nseg * g.segK / BK;

    auto issue_tile = [&](int kt, int st) {
        int k0 = kt * BK;
        int seg = k0 / g.segK;
        int koff = k0 - seg * g.segK;
        const __half* A = g.A[seg];
        const __half* W = g.W[seg];

        uint32_t a_s = smem_base + st * STAGE_BYTES + ld_row * (ASTH * 2);
        const __half* a_g = A + (size_t)a_grow * g.segK + koff;
        int a_sz = a_ok ? 16 : 0;
        #pragma unroll
        for (int c = 0; c < 2; c++)
            cp_async16(a_s + (cb + c) * 16, a_g + (cb + c) * 8, a_sz);

        uint32_t w_s = smem_base + st * STAGE_BYTES + A_STAGE_BYTES + ld_row * (WPAD * 2);
        const __half* w_g = W + (size_t)(n0 + ld_row) * g.segK + koff;
        #pragma unroll
        for (int c = 0; c < 2; c++)
            cp_async16(w_s + (cb + c) * 16, w_g + (cb + c) * 8, 16);

        cp_commit();
    };

    float acc[2][8][4];
    #pragma unroll
    for (int i = 0; i < 2; i++)
        #pragma unroll
        for (int j = 0; j < 8; j++)
            #pragma unroll
            for (int c = 0; c < 4; c++) acc[i][j][c] = 0.f;

    issue_tile(0, 0);

    for (int kt = 0; kt < ktiles; kt++) {
        int st = kt & 1;
        if (kt + 1 < ktiles) {
            issue_tile(kt + 1, (kt + 1) & 1);
            cp_wait<1>();
        } else {
            cp_wait<0>();
        }
        __syncthreads();

        const __half* As = (const __half*)(smem_c + st * STAGE_BYTES);
        const __half* Ws = (const __half*)(smem_c + st * STAGE_BYTES + A_STAGE_BYTES);

        #pragma unroll
        for (int ks = 0; ks < BK / 16; ks++) {
            int kb = ks * 16;
            uint32_t afr[2][4];
            #pragma unroll
            for (int mi = 0; mi < 2; mi++) {
                int r = wm + mi * 16 + grp;
                afr[mi][0] = *(const uint32_t*)(As + r * ASTH + kb + 2 * tg);
                afr[mi][1] = *(const uint32_t*)(As + (r + 8) * ASTH + kb + 2 * tg);
                afr[mi][2] = *(const uint32_t*)(As + r * ASTH + kb + 8 + 2 * tg);
                afr[mi][3] = *(const uint32_t*)(As + (r + 8) * ASTH + kb + 8 + 2 * tg);
            }
            uint32_t bfr[8][2];
            #pragma unroll
            for (int nt = 0; nt < 8; nt++) {
                int nb = wn + nt * 8 + grp;
                bfr[nt][0] = *(const uint32_t*)(Ws + nb * WPAD + kb + 2 * tg);
                bfr[nt][1] = *(const uint32_t*)(Ws + nb * WPAD + kb + 8 + 2 * tg);
            }
            #pragma unroll
            for (int mi = 0; mi < 2; mi++) {
                #pragma unroll
                for (int nt = 0; nt < 8; nt++) {
                    asm volatile(
                        "mma.sync.aligned.m16n8k16.row.col.f32.f16.f16.f32 "
                        "{%0,%1,%2,%3}, {%4,%5,%6,%7}, {%8,%9}, {%0,%1,%2,%3};"
                        : "+f"(acc[mi][nt][0]), "+f"(acc[mi][nt][1]),
                          "+f"(acc[mi][nt][2]), "+f"(acc[mi][nt][3])
                        : "r"(afr[mi][0]), "r"(afr[mi][1]),
                          "r"(afr[mi][2]), "r"(afr[mi][3]),
                          "r"(bfr[nt][0]), "r"(bfr[nt][1]));
                }
            }
        }
        __syncthreads();
    }

    float bias[8][2];
    #pragma unroll
    for (int nt = 0; nt < 8; nt++) {
        int c = n0 + wn + nt * 8 + tg * 2;
        float b0v = 0.f, b1v = 0.f;
        if (g.b0) { b0v = g.b0[c] + (g.b1 ? g.b1[c] : 0.f); }
        if (g.b0) { b1v = g.b0[c + 1] + (g.b1 ? g.b1[c + 1] : 0.f); }
        bias[nt][0] = b0v;
        bias[nt][1] = b1v;
    }

    if (g.headmode) {
        float* red = (float*)smem_c;
        for (int i = tid; i < BM; i += 256) red[i] = 0.f;
        __syncthreads();
        #pragma unroll
        for (int mi = 0; mi < 2; mi++) {
            float p0 = 0.f, p1 = 0.f;
            #pragma unroll
            for (int nt = 0; nt < 8; nt++) {
                int c = n0 + wn + nt * 8 + tg * 2;
                float w20 = g.w2[c], w21 = g.w2[c + 1];
                float v00 = fmaxf(acc[mi][nt][0] + bias[nt][0], 0.f);
                float v01 = fmaxf(acc[mi][nt][1] + bias[nt][1], 0.f);
                float v10 = fmaxf(acc[mi][nt][2] + bias[nt][0], 0.f);
                float v11 = fmaxf(acc[mi][nt][3] + bias[nt][1], 0.f);
                p0 += v00 * w20 + v01 * w21;
                p1 += v10 * w20 + v11 * w21;
            }
            atomicAdd(&red[wm + mi * 16 + grp], p0);
            atomicAdd(&red[wm + mi * 16 + grp + 8], p1);
        }
        __syncthreads();
        if (tid < BM) {
            int row = m0 + tid;
            if (row < g.M) {
                int off = (n0 >= HHALF) ? NTX : 0;
                float b2 = (n0 >= HHALF) ? g.b2v[0] : g.b2c[0];
                ((float*)g.C)[off + row] = red[tid] + b2;
            }
        }
        return;
    }

    #pragma unroll
    for (int mi = 0; mi < 2; mi++) {
        int r0 = m0 + wm + mi * 16 + grp;
        int r1 = r0 + 8;
        #pragma unroll
        for (int nt = 0; nt < 8; nt++) {
            int c = n0 + wn + nt * 8 + tg * 2;
            #pragma unroll
            for (int half_idx = 0; half_idx < 2; half_idx++) {
                int r = half_idx ? r1 : r0;
                if (r >= g.M) continue;
                float a0 = half_idx ? acc[mi][nt][2] : acc[mi][nt][0];
                float a1 = half_idx ? acc[mi][nt][3] : acc[mi][nt][1];
                float e0 = 0.f, e1 = 0.f;
                if (g.E0) {
                    float2 t = *(const float2*)(g.E0 + (size_t)r * g.N + c);
                    e0 = t.x; e1 = t.y;
                }
                float v0 = (a0 + bias[nt][0] + e0) * g.outscale;
                float v1 = (a1 + bias[nt][1] + e1) * g.outscale;
                if (g.relu) { v0 = fmaxf(v0, 0.f); v1 = fmaxf(v1, 0.f); }
                if (g.out_half) {
                    *(__half2*)((__half*)g.C + (size_t)r * g.N + c) = __floats2half2_rn(v0, v1);
                } else {
                    *(float2*)((float*)g.C + (size_t)r * g.N + c) = make_float2(v0, v1);
                }
            }
        }
    }
}

// ---------------------------------------------------------------------------
// Host orchestration: round-9 schedule + fp16 activation path
// ---------------------------------------------------------------------------
static inline int ceil_div(int a, int b) { return (a + b - 1) / b; }

extern "C" void kernel_launch(void* const* d_in, const int* in_sizes, int n_in,
                              void* d_out, int out_size) {
    const float* x_tx   = (const float*)d_in[0];
    const float* x_user = (const float*)d_in[1];
    const float* x_merch= (const float*)d_in[2];
    const float* Wp     = (const float*)d_in[3];
    const float* bp     = (const float*)d_in[4];
    const float* Wl     = (const float*)d_in[5];
    const float* bl     = (const float*)d_in[6];
    const float* Wr     = (const float*)d_in[7];
    const float* Wc1    = (const float*)d_in[8];
    const float* bc1    = (const float*)d_in[9];
    const float* Wc2    = (const float*)d_in[10];
    const float* bc2    = (const float*)d_in[11];
    const float* Wv1    = (const float*)d_in[12];
    const float* bv1    = (const float*)d_in[13];
    const float* Wv2    = (const float*)d_in[14];
    const float* bv2    = (const float*)d_in[15];
    const int* e_ut_src = (const int*)d_in[16];
    const int* e_ut_dst = (const int*)d_in[17];
    const int* e_tm_src = (const int*)d_in[18];
    const int* e_tm_dst = (const int*)d_in[19];
    const int* e_mt_src = (const int*)d_in[20];
    const int* e_mt_dst = (const int*)d_in[21];
    const int* e_tu_src = (const int*)d_in[22];
    const int* e_tu_dst = (const int*)d_in[23];
    float* out = (float*)d_out;

    WS* ws = nullptr;
    cudaGetSymbolAddress((void**)&ws, g_ws);

    static cudaStream_t sB = nullptr, sC = nullptr;
    static cudaEvent_t ev[10];
    if (!sB) {
        cudaStreamCreateWithFlags(&sB, cudaStreamNonBlocking);
        cudaStreamCreateWithFlags(&sC, cudaStreamNonBlocking);
        for (int i = 0; i < 10; i++)
            cudaEventCreateWithFlags(&ev[i], cudaEventDisableTiming);
        cudaFuncSetAttribute(gemm_fp16, cudaFuncAttributeMaxDynamicSharedMemorySize,
                             GEMM_SMEM_BYTES);
    }
    cudaStream_t s0 = 0;
    cudaEvent_t evFork0 = ev[0], evPrep = ev[1], evCsr = ev[2], evProj = ev[3];
    cudaEvent_t evY0 = ev[4], evYm1 = ev[5], evGts1 = ev[6];

    const float* bl0_0 = bl + 0 * HDIM;
    const float* bl1_0 = bl + 1 * HDIM;
    const float* bl2_0 = bl + 2 * HDIM;
    const float* bl3_0 = bl + 3 * HDIM;
    const float* bl0_1 = bl + 4 * HDIM;
    const float* bl2_1 = bl + 6 * HDIM;

    cudaEventRecord(evFork0, s0);
    cudaStreamWaitEvent(sB, evFork0, 0);
    cudaStreamWaitEvent(sC, evFork0, 0);

    // ======== s0: x_tx fp16 convert (independent of sC weight prep) ========
    conv_x<<<ceil_div(NTX * FIN / 4, 256), 256, 0, s0>>>(x_tx, ws->xtx_h, NTX * FIN / 4);

    // ======== sC: weight + activation prep ========
    int cg = ceil_div(HDIM * HDIM, 256);
    conv_all<<<dim3(cg, 9), 256, 0, sC>>>(Wl, Wr, Wp);
    prep_wsum_h<<<dim3(cg, 2), 256, 0, sC>>>(Wr);
    prep_wcat_h<<<cg, 256, 0, sC>>>(Wc1, Wv1, bc1, bv1, Wc2, Wv2);
    conv_x<<<ceil_div(NUSER * HDIM / 4, 256), 256, 0, sC>>>(x_user, ws->xu_h, NUSER * HDIM / 4);
    conv_x<<<ceil_div(NMERCH * HDIM / 4, 256), 256, 0, sC>>>(x_merch, ws->xm_h, NMERCH * HDIM / 4);
    cudaEventRecord(evPrep, sC);

    // ======== sB: CSR build ========
    cudaMemsetAsync(ws->deg,    0, sizeof(ws->deg),    sB);
    cudaMemsetAsync(ws->cursor, 0, sizeof(ws->cursor), sB);
    build_count<<<dim3(ceil_div(NEDGE, 256), 4), 256, 0, sB>>>(e_ut_dst, e_tm_dst, e_mt_dst, e_tu_dst);
    scan4<<<4, 1024, 0, sB>>>(NTX, NMERCH, NTX, NUSER);
    build_fill<<<dim3(ceil_div(NEDGE, 256), 4), 256, 0, sB>>>(e_ut_src, e_ut_dst, e_tm_src, e_tm_dst,
                                                              e_mt_src, e_mt_dst, e_tu_src, e_tu_dst);
    cudaEventRecord(evCsr, sB);

    // ======== s0: proj (needs xtx_h + wp_h) ========
    cudaStreamWaitEvent(s0, evPrep, 0);
    {
        GemmArgs a = {};
        a.A[0] = ws->xtx_h; a.W[0] = ws->wp_h; a.b0 = bp;
        a.C = ws->xth[0]; a.M = NTX; a.N = HDIM; a.nseg = 1; a.segK = FIN;
        a.outscale = 1.0f; a.relu = 0; a.out_half = 1;
        gemm_fp16<<<dim3(ceil_div(NTX, BM), HDIM / BN), 256, GEMM_SMEM_BYTES, s0>>>(a);
    }
    cudaEventRecord(evProj, s0);

    // ======== sB (cont): mm0 -> xm1 -> ym1 ========
    cudaStreamWaitEvent(sB, evProj, 0);
    seg_mean_h<<<ceil_div(NMERCH * 32, 256), 256, 0, sB>>>(ws->xth[0], 1, ws->mmh, NMERCH);
    {
        GemmArgs a = {};
        a.A[0] = ws->mmh;  a.W[0] = ws->wl1h;
        a.A[1] = ws->xm_h; a.W[1] = ws->wr1h;
        a.b0 = bl1_0;
        a.C = ws->xm1h; a.M = NMERCH; a.N = HDIM; a.nseg = 2; a.segK = HDIM;
        a.outscale = 1.0f; a.relu = 1; a.out_half = 1;
        gemm_fp16<<<dim3(ceil_div(NMERCH, BM), HDIM / BN), 256, GEMM_SMEM_BYTES, sB>>>(a);
    }
    {
        GemmArgs a = {};
        a.A[0] = ws->xm1h; a.W[0] = ws->wl2h[1];
        a.C = ws->ym[1]; a.M = NMERCH; a.N = HDIM; a.nseg = 1; a.segK = HDIM;
        a.outscale = 1.0f; a.relu = 0; a.out_half = 0;
        gemm_fp16<<<dim3(ceil_div(NMERCH, BM), HDIM / BN), 256, GEMM_SMEM_BYTES, sB>>>(a);
    }
    cudaEventRecord(evYm1, sB);

    // ======== sC (cont): yu0/ym0, mu0 -> xu1 -> yu1 -> dual1 ========
    {
        GemmArgs a = {};
        a.A[0] = ws->xu_h; a.W[0] = ws->wl0h[0];
        a.C = ws->yu[0]; a.M = NUSER; a.N = HDIM; a.nseg = 1; a.segK = HDIM;
        a.outscale = 1.0f; a.relu = 0; a.out_half = 0;
        gemm_fp16<<<dim3(ceil_div(NUSER, BM), HDIM / BN), 256, GEMM_SMEM_BYTES, sC>>>(a);
    }
    {
        GemmArgs a = {};
        a.A[0] = ws->xm_h; a.W[0] = ws->wl2h[0];
        a.C = ws->ym[0]; a.M = NMERCH; a.N = HDIM; a.nseg = 1; a.segK = HDIM;
        a.outscale = 1.0f; a.relu = 0; a.out_half = 0;
        gemm_fp16<<<dim3(ceil_div(NMERCH, BM), HDIM / BN), 256, GEMM_SMEM_BYTES, sC>>>(a);
    }
    cudaEventRecord(evY0, sC);
    cudaStreamWaitEvent(sC, evCsr, 0);
    cudaStreamWaitEvent(sC, evProj, 0);
    seg_mean_h<<<ceil_div(NUSER * 32, 256), 256, 0, sC>>>(ws->xth[0], 3, ws->muh, NUSER);
    {
        GemmArgs a = {};
        a.A[0] = ws->muh;  a.W[0] = ws->wl3h;
        a.A[1] = ws->xu_h; a.W[1] = ws->wr3h;
        a.b0 = bl3_0;
        a.C = ws->xu1h; a.M = NUSER; a.N = HDIM; a.nseg = 2; a.segK = HDIM;
        a.outscale = 1.0f; a.relu = 1; a.out_half = 1;
        gemm_fp16<<<dim3(ceil_div(NUSER, BM), HDIM / BN), 256, GEMM_SMEM_BYTES, sC>>>(a);
    }
    {
        GemmArgs a = {};
        a.A[0] = ws->xu1h; a.W[0] = ws->wl0h[1];
        a.C = ws->yu[1]; a.M = NUSER; a.N = HDIM; a.nseg = 1; a.segK = HDIM;
        a.outscale = 1.0f; a.relu = 0; a.out_half = 0;
        gemm_fp16<<<dim3(ceil_div(NUSER, BM), HDIM / BN), 256, GEMM_SMEM_BYTES, sC>>>(a);
    }
    cudaStreamWaitEvent(sC, evYm1, 0);
    seg_mean_dual<<<ceil_div(NTX * 32, 256), 256, 0, sC>>>(ws->yu[1], ws->ym[1], ws->gts[1]);
    cudaEventRecord(evGts1, sC);

    // ======== s0 (cont): dual0 -> xtL0 -> xtL1 -> fused head ========
    cudaStreamWaitEvent(s0, evY0, 0);
    cudaStreamWaitEvent(s0, evCsr, 0);
    seg_mean_dual<<<ceil_div(NTX * 32, 256), 256, 0, s0>>>(ws->yu[0], ws->ym[0], ws->gts[0]);
    {
        GemmArgs a = {};
        a.A[0] = ws->xth[0]; a.W[0] = ws->wsum_h[0];
        a.b0 = bl0_0; a.b1 = bl2_0;
        a.E0 = ws->gts[0];
        a.C = ws->xth[1]; a.M = NTX; a.N = HDIM; a.nseg = 1; a.segK = HDIM;
        a.outscale = 0.5f; a.relu = 1; a.out_half = 1;
        gemm_fp16<<<dim3(ceil_div(NTX, BM), HDIM / BN), 256, GEMM_SMEM_BYTES, s0>>>(a);
    }
    cudaStreamWaitEvent(s0, evGts1, 0);
    {
        GemmArgs a = {};
        a.A[0] = ws->xth[1]; a.W[0] = ws->wsum_h[1];
        a.b0 = bl0_1; a.b1 = bl2_1;
        a.E0 = ws->gts[1];
        a.C = ws->xth[0]; a.M = NTX; a.N = HDIM; a.nseg = 1; a.segK = HDIM;
        a.outscale = 0.5f; a.relu = 1; a.out_half = 1;
        gemm_fp16<<<dim3(ceil_div(NTX, BM), HDIM / BN), 256, GEMM_SMEM_BYTES, s0>>>(a);
    }
    {
        GemmArgs a = {};
        a.A[0] = ws->xth[0]; a.W[0] = ws->wcat_h; a.b0 = ws->bcat;
        a.C = out; a.M = NTX; a.N = HDIM; a.nseg = 1; a.segK = HDIM;
        a.outscale = 1.0f; a.relu = 1;
        a.headmode = 1; a.w2 = ws->w2cat; a.b2c = bc2; a.b2v = bv2;
        gemm_fp16<<<dim3(ceil_div(NTX, BM), HDIM / BN), 256, GEMM_SMEM_BYTES, s0>>>(a);
    }
}

// round 12
// speedup vs baseline: 1.1954x; 1.0396x over previous
#include <cuda_runtime.h>
#include <cuda_fp16.h>
#include <cstdint>

#define NTX    100000
#define NUSER  20000
#define NMERCH 5000
#define NEDGE  400000
#define HDIM   256
#define HHALF  128
#define FIN    32

// ---------------------------------------------------------------------------
// Workspace (single __device__ global; no allocations allowed)
// ---------------------------------------------------------------------------
struct WS {
    // fp16 activations
    __half xth[2][NTX * HDIM];
    __half xtx_h [NTX * FIN];
    __half xu_h  [NUSER * HDIM];
    __half xm_h  [NMERCH * HDIM];
    __half mmh [NMERCH * HDIM];
    __half muh [NUSER * HDIM];
    __half xm1h[NMERCH * HDIM];
    __half xu1h[NUSER * HDIM];
    __half yuh [2][NUSER * HDIM];    // xu@Wl0 per layer (fp16, gather source)
    __half ymh [2][NMERCH * HDIM];   // xm@Wl2 per layer (fp16, gather source)
    // fp32 (epilogue addend — precision-critical)
    float gts[2][NTX * HDIM];
    float bcat[HDIM];
    float w2cat[HDIM];
    // fp16 weights, transposed to [n][k]
    __half wp_h  [HDIM * FIN];
    __half wl0h[2][HDIM * HDIM];
    __half wl2h[2][HDIM * HDIM];
    __half wl1h  [HDIM * HDIM];
    __half wr1h  [HDIM * HDIM];
    __half wl3h  [HDIM * HDIM];
    __half wr3h  [HDIM * HDIM];
    __half wsum_h[2][HDIM * HDIM];
    __half wcat_h[HDIM * HDIM];
    int deg   [4][NTX];
    int cursor[4][NTX];
    int rowptr[4][NTX + 1];
    int perm  [4][NEDGE];
};
__device__ WS g_ws;

// relations: 0 = user->tx, 1 = tx->merch, 2 = merch->tx, 3 = tx->user
// ---------------------------------------------------------------------------
// CSR build
// ---------------------------------------------------------------------------
__global__ void build_count(const int* __restrict__ d0, const int* __restrict__ d1,
                            const int* __restrict__ d2, const int* __restrict__ d3) {
    int i = blockIdx.x * blockDim.x + threadIdx.x;
    if (i >= NEDGE) return;
    int rel = blockIdx.y;
    const int* d = (rel == 0) ? d0 : (rel == 1) ? d1 : (rel == 2) ? d2 : d3;
    atomicAdd(&g_ws.deg[rel][d[i]], 1);
}

__global__ void scan4(int n0, int n1, int n2, int n3) {
    int rel = blockIdx.x;
    int n = (rel == 0) ? n0 : (rel == 1) ? n1 : (rel == 2) ? n2 : n3;
    const int* deg = g_ws.deg[rel];
    int* rp = g_ws.rowptr[rel];
    __shared__ int wsum[32];
    __shared__ int s_carry;
    int tid = threadIdx.x, lane = tid & 31, wid = tid >> 5;
    if (tid == 0) s_carry = 0;
    __syncthreads();
    for (int base = 0; base < n; base += 1024) {
        int i = base + tid;
        int v = (i < n) ? deg[i] : 0;
        int x = v;
        #pragma unroll
        for (int off = 1; off < 32; off <<= 1) {
            int u = __shfl_up_sync(0xffffffffu, x, off);
            if (lane >= off) x += u;
        }
        if (lane == 31) wsum[wid] = x;
        __syncthreads();
        if (wid == 0) {
            int w = wsum[lane];
            int y = w;
            #pragma unroll
            for (int off = 1; off < 32; off <<= 1) {
                int u = __shfl_up_sync(0xffffffffu, y, off);
                if (lane >= off) y += u;
            }
            wsum[lane] = y - w;
        }
        __syncthreads();
        int incl = x + wsum[wid];
        int c = s_carry;
        __syncthreads();
        if (i < n) rp[i] = c + incl - v;
        if (tid == 1023) s_carry = c + incl;
        __syncthreads();
    }
    if (tid == 0) rp[n] = s_carry;
}

__global__ void build_fill(const int* __restrict__ s0, const int* __restrict__ d0,
                           const int* __restrict__ s1, const int* __restrict__ d1,
                           const int* __restrict__ s2, const int* __restrict__ d2,
                           const int* __restrict__ s3, const int* __restrict__ d3) {
    int i = blockIdx.x * blockDim.x + threadIdx.x;
    if (i >= NEDGE) return;
    int rel = blockIdx.y;
    const int* s = (rel == 0) ? s0 : (rel == 1) ? s1 : (rel == 2) ? s2 : s3;
    const int* d = (rel == 0) ? d0 : (rel == 1) ? d1 : (rel == 2) ? d2 : d3;
    int dst = d[i];
    int pos = g_ws.rowptr[rel][dst] + atomicAdd(&g_ws.cursor[rel][dst], 1);
    g_ws.perm[rel][pos] = s[i];
}

// ---------------------------------------------------------------------------
// Prep kernels
// ---------------------------------------------------------------------------
__global__ void conv_all(const float* __restrict__ Wl, const float* __restrict__ Wr,
                         const float* __restrict__ Wp) {
    int m = blockIdx.y;
    int i = blockIdx.x * blockDim.x + threadIdx.x;
    if (m == 0) {
        if (i >= HDIM * FIN) return;
        int n = i / FIN, k = i % FIN;
        g_ws.wp_h[i] = __float2half(Wp[k * HDIM + n]);
        return;
    }
    if (i >= HDIM * HDIM) return;
    const float* src;
    __half* dst;
    const size_t S = (size_t)HDIM * HDIM;
    switch (m) {
        case 1: src = Wl + 0 * S; dst = g_ws.wl0h[0]; break;
        case 2: src = Wl + 2 * S; dst = g_ws.wl2h[0]; break;
        case 3: src = Wl + 4 * S; dst = g_ws.wl0h[1]; break;
        case 4: src = Wl + 6 * S; dst = g_ws.wl2h[1]; break;
        case 5: src = Wl + 1 * S; dst = g_ws.wl1h;    break;
        case 6: src = Wr + 1 * S; dst = g_ws.wr1h;    break;
        case 7: src = Wl + 3 * S; dst = g_ws.wl3h;    break;
        default: src = Wr + 3 * S; dst = g_ws.wr3h;   break;
    }
    int n = i >> 8, k = i & 255;
    dst[i] = __float2half(src[k * HDIM + n]);
}

__global__ void prep_wsum_h(const float* __restrict__ Wr) {
    int i = blockIdx.x * blockDim.x + threadIdx.x;
    if (i >= HDIM * HDIM) return;
    int l = blockIdx.y;
    int n = i >> 8, k = i & 255;
    const float* Wr0 = Wr + ((size_t)(l * 4 + 0)) * HDIM * HDIM;
    const float* Wr2 = Wr + ((size_t)(l * 4 + 2)) * HDIM * HDIM;
    g_ws.wsum_h[l][i] = __float2half(Wr0[k * HDIM + n] + Wr2[k * HDIM + n]);
}

__global__ void prep_wcat_h(const float* __restrict__ Wc1, const float* __restrict__ Wv1,
                            const float* __restrict__ bc1, const float* __restrict__ bv1,
                            const float* __restrict__ Wc2, const float* __restrict__ Wv2) {
    int i = blockIdx.x * blockDim.x + threadIdx.x;
    if (i < HDIM * HDIM) {
        int n = i >> 8, k = i & 255;
        float v = (n < HHALF) ? Wc1[k * HHALF + n] : Wv1[k * HHALF + (n - HHALF)];
        g_ws.wcat_h[i] = __float2half(v);
    }
    if (i < HDIM) {
        g_ws.bcat[i]  = (i < HHALF) ? bc1[i] : bv1[i - HHALF];
        g_ws.w2cat[i] = (i < HHALF) ? Wc2[i] : Wv2[i - HHALF];
    }
}

__global__ void conv_x(const float* __restrict__ x, __half* __restrict__ y, int n4) {
    int i = blockIdx.x * blockDim.x + threadIdx.x;
    if (i >= n4) return;
    float4 v = ((const float4*)x)[i];
    ((__half2*)y)[i * 2 + 0] = __floats2half2_rn(v.x, v.y);
    ((__half2*)y)[i * 2 + 1] = __floats2half2_rn(v.z, v.w);
}

// ---------------------------------------------------------------------------
// Segment-mean kernels
// ---------------------------------------------------------------------------
// half in -> half out (fp32 accumulation)
__global__ void seg_mean_h(const __half* __restrict__ xsrc, int rel,
                           __half* __restrict__ outm, int n_dst) {
    int w = (blockIdx.x * blockDim.x + threadIdx.x) >> 5;
    int lane = threadIdx.x & 31;
    if (w >= n_dst) return;
    const int* __restrict__ rp = g_ws.rowptr[rel];
    const int* __restrict__ pm = g_ws.perm[rel];
    int beg = rp[w], end = rp[w + 1];
    float acc[8];
    #pragma unroll
    for (int j = 0; j < 8; j++) acc[j] = 0.f;
    for (int e = beg; e < end; e++) {
        int s = pm[e];
        uint4 v = ((const uint4*)(xsrc + (size_t)s * HDIM))[lane];
        const __half2* h = (const __half2*)&v;
        #pragma unroll
        for (int j = 0; j < 4; j++) {
            float2 f = __half22float2(h[j]);
            acc[j * 2 + 0] += f.x;
            acc[j * 2 + 1] += f.y;
        }
    }
    float inv = 1.0f / (float)max(end - beg, 1);
    uint4 o;
    __half2* oh = (__half2*)&o;
    #pragma unroll
    for (int j = 0; j < 4; j++)
        oh[j] = __floats2half2_rn(acc[j * 2] * inv, acc[j * 2 + 1] * inv);
    ((uint4*)(outm + (size_t)w * HDIM))[lane] = o;
}

// fp16 dual gather: gts = mean_rel0(ya) + mean_rel2(yb), fp32 accumulation+output
__global__ void seg_mean_dual_h(const __half* __restrict__ ya, const __half* __restrict__ yb,
                                float* __restrict__ outm) {
    int w = (blockIdx.x * blockDim.x + threadIdx.x) >> 5;
    int lane = threadIdx.x & 31;
    if (w >= NTX) return;

    float r[8];
    #pragma unroll
    for (int j = 0; j < 8; j++) r[j] = 0.f;

    {
        const int* __restrict__ rp = g_ws.rowptr[0];
        const int* __restrict__ pm = g_ws.perm[0];
        int beg = rp[w], end = rp[w + 1];
        float a[8];
        #pragma unroll
        for (int j = 0; j < 8; j++) a[j] = 0.f;
        for (int e = beg; e < end; e++) {
            int s = pm[e];
            uint4 v = ((const uint4*)(ya + (size_t)s * HDIM))[lane];
            const __half2* h = (const __half2*)&v;
            #pragma unroll
            for (int j = 0; j < 4; j++) {
                float2 f = __half22float2(h[j]);
                a[j * 2 + 0] += f.x;
                a[j * 2 + 1] += f.y;
            }
        }
        float inv = 1.0f / (float)max(end - beg, 1);
        #pragma unroll
        for (int j = 0; j < 8; j++) r[j] += a[j] * inv;
    }
    {
        const int* __restrict__ rp = g_ws.rowptr[2];
        const int* __restrict__ pm = g_ws.perm[2];
        int beg = rp[w], end = rp[w + 1];
        float a[8];
        #pragma unroll
        for (int j = 0; j < 8; j++) a[j] = 0.f;
        for (int e = beg; e < end; e++) {
            int s = pm[e];
            uint4 v = ((const uint4*)(yb + (size_t)s * HDIM))[lane];
            const __half2* h = (const __half2*)&v;
            #pragma unroll
            for (int j = 0; j < 4; j++) {
                float2 f = __half22float2(h[j]);
                a[j * 2 + 0] += f.x;
                a[j * 2 + 1] += f.y;
            }
        }
        float inv = 1.0f / (float)max(end - beg, 1);
        #pragma unroll
        for (int j = 0; j < 8; j++) r[j] += a[j] * inv;
    }

    float* o = outm + (size_t)w * HDIM + lane * 8;
    *(float4*)(o + 0) = make_float4(r[0], r[1], r[2], r[3]);
    *(float4*)(o + 4) = make_float4(r[4], r[5], r[6], r[7]);
}

// ---------------------------------------------------------------------------
// Fused GEMM: fp16 A/W, fp32 acc, cp.async double-buffered; fp32/fp16 out,
// optional fp32 E0 add, optional fused head.
// ---------------------------------------------------------------------------
#define BM 128
#define BN 128
#define BK 32
#define ASTH 40
#define WPAD 56
#define A_STAGE_BYTES (BM * ASTH * 2)
#define W_STAGE_BYTES (BN * WPAD * 2)
#define STAGE_BYTES (A_STAGE_BYTES + W_STAGE_BYTES)
#define GEMM_SMEM_BYTES (2 * STAGE_BYTES)

struct GemmArgs {
    const __half* A[2];
    const __half* W[2];
    const float* b0;
    const float* b1;
    const float* E0;
    void* C;
    int M, N, nseg, segK;
    float outscale;
    int relu;
    int out_half;
    int headmode;
    const float* w2;
    const float* b2c;
    const float* b2v;
};

__device__ __forceinline__ void cp_async16(uint32_t smem_addr, const void* gptr, int src_bytes) {
    asm volatile("cp.async.cg.shared.global [%0], [%1], 16, %2;"
                 :: "r"(smem_addr), "l"(gptr), "r"(src_bytes));
}
__device__ __forceinline__ void cp_commit() {
    asm volatile("cp.async.commit_group;");
}
template <int N>
__device__ __forceinline__ void cp_wait() {
    asm volatile("cp.async.wait_group %0;" :: "n"(N));
}

__global__ void __launch_bounds__(256, 2) gemm_fp16(GemmArgs g) {
    extern __shared__ char smem_c[];

    int tid = threadIdx.x;
    int lane = tid & 31;
    int warp = tid >> 5;
    int wm = (warp & 3) * 32;
    int wn = (warp >> 2) * 64;
    int grp = lane >> 2;
    int tg  = lane & 3;

    int m0 = blockIdx.x * BM, n0 = blockIdx.y * BN;

    int ld_row = tid >> 1;
    int cb = (tid & 1) * 2;

    int a_grow = m0 + ld_row;
    bool a_ok = (a_grow < g.M);

    uint32_t smem_base = (uint32_t)__cvta_generic_to_shared(smem_c);
    int ktiles = g.nseg * g.segK / BK;

    auto issue_tile = [&](int kt, int st) {
        int k0 = kt * BK;
        int seg = k0 / g.segK;
        int koff = k0 - seg * g.segK;
        const __half* A = g.A[seg];
        const __half* W = g.W[seg];

        uint32_t a_s = smem_base + st * STAGE_BYTES + ld_row * (ASTH * 2);
        const __half* a_g = A + (size_t)a_grow * g.segK + koff;
        int a_sz = a_ok ? 16 : 0;
        #pragma unroll
        for (int c = 0; c < 2; c++)
            cp_async16(a_s + (cb + c) * 16, a_g + (cb + c) * 8, a_sz);

        uint32_t w_s = smem_base + st * STAGE_BYTES + A_STAGE_BYTES + ld_row * (WPAD * 2);
        const __half* w_g = W + (size_t)(n0 + ld_row) * g.segK + koff;
        #pragma unroll
        for (int c = 0; c < 2; c++)
            cp_async16(w_s + (cb + c) * 16, w_g + (cb + c) * 8, 16);

        cp_commit();
    };

    float acc[2][8][4];
    #pragma unroll
    for (int i = 0; i < 2; i++)
        #pragma unroll
        for (int j = 0; j < 8; j++)
            #pragma unroll
            for (int c = 0; c < 4; c++) acc[i][j][c] = 0.f;

    issue_tile(0, 0);

    for (int kt = 0; kt < ktiles; kt++) {
        int st = kt & 1;
        if (kt + 1 < ktiles) {
            issue_tile(kt + 1, (kt + 1) & 1);
            cp_wait<1>();
        } else {
            cp_wait<0>();
        }
        __syncthreads();

        const __half* As = (const __half*)(smem_c + st * STAGE_BYTES);
        const __half* Ws = (const __half*)(smem_c + st * STAGE_BYTES + A_STAGE_BYTES);

        #pragma unroll
        for (int ks = 0; ks < BK / 16; ks++) {
            int kb = ks * 16;
            uint32_t afr[2][4];
            #pragma unroll
            for (int mi = 0; mi < 2; mi++) {
                int r = wm + mi * 16 + grp;
                afr[mi][0] = *(const uint32_t*)(As + r * ASTH + kb + 2 * tg);
                afr[mi][1] = *(const uint32_t*)(As + (r + 8) * ASTH + kb + 2 * tg);
                afr[mi][2] = *(const uint32_t*)(As + r * ASTH + kb + 8 + 2 * tg);
                afr[mi][3] = *(const uint32_t*)(As + (r + 8) * ASTH + kb + 8 + 2 * tg);
            }
            uint32_t bfr[8][2];
            #pragma unroll
            for (int nt = 0; nt < 8; nt++) {
                int nb = wn + nt * 8 + grp;
                bfr[nt][0] = *(const uint32_t*)(Ws + nb * WPAD + kb + 2 * tg);
                bfr[nt][1] = *(const uint32_t*)(Ws + nb * WPAD + kb + 8 + 2 * tg);
            }
            #pragma unroll
            for (int mi = 0; mi < 2; mi++) {
                #pragma unroll
                for (int nt = 0; nt < 8; nt++) {
                    asm volatile(
                        "mma.sync.aligned.m16n8k16.row.col.f32.f16.f16.f32 "
                        "{%0,%1,%2,%3}, {%4,%5,%6,%7}, {%8,%9}, {%0,%1,%2,%3};"
                        : "+f"(acc[mi][nt][0]), "+f"(acc[mi][nt][1]),
                          "+f"(acc[mi][nt][2]), "+f"(acc[mi][nt][3])
                        : "r"(afr[mi][0]), "r"(afr[mi][1]),
                          "r"(afr[mi][2]), "r"(afr[mi][3]),
                          "r"(bfr[nt][0]), "r"(bfr[nt][1]));
                }
            }
        }
        __syncthreads();
    }

    float bias[8][2];
    #pragma unroll
    for (int nt = 0; nt < 8; nt++) {
        int c = n0 + wn + nt * 8 + tg * 2;
        float b0v = 0.f, b1v = 0.f;
        if (g.b0) { b0v = g.b0[c] + (g.b1 ? g.b1[c] : 0.f); }
        if (g.b0) { b1v = g.b0[c + 1] + (g.b1 ? g.b1[c + 1] : 0.f); }
        bias[nt][0] = b0v;
        bias[nt][1] = b1v;
    }

    if (g.headmode) {
        float* red = (float*)smem_c;
        for (int i = tid; i < BM; i += 256) red[i] = 0.f;
        __syncthreads();
        #pragma unroll
        for (int mi = 0; mi < 2; mi++) {
            float p0 = 0.f, p1 = 0.f;
            #pragma unroll
            for (int nt = 0; nt < 8; nt++) {
                int c = n0 + wn + nt * 8 + tg * 2;
                float w20 = g.w2[c], w21 = g.w2[c + 1];
                float v00 = fmaxf(acc[mi][nt][0] + bias[nt][0], 0.f);
                float v01 = fmaxf(acc[mi][nt][1] + bias[nt][1], 0.f);
                float v10 = fmaxf(acc[mi][nt][2] + bias[nt][0], 0.f);
                float v11 = fmaxf(acc[mi][nt][3] + bias[nt][1], 0.f);
                p0 += v00 * w20 + v01 * w21;
                p1 += v10 * w20 + v11 * w21;
            }
            atomicAdd(&red[wm + mi * 16 + grp], p0);
            atomicAdd(&red[wm + mi * 16 + grp + 8], p1);
        }
        __syncthreads();
        if (tid < BM) {
            int row = m0 + tid;
            if (row < g.M) {
                int off = (n0 >= HHALF) ? NTX : 0;
                float b2 = (n0 >= HHALF) ? g.b2v[0] : g.b2c[0];
                ((float*)g.C)[off + row] = red[tid] + b2;
            }
        }
        return;
    }

    #pragma unroll
    for (int mi = 0; mi < 2; mi++) {
        int r0 = m0 + wm + mi * 16 + grp;
        int r1 = r0 + 8;
        #pragma unroll
        for (int nt = 0; nt < 8; nt++) {
            int c = n0 + wn + nt * 8 + tg * 2;
            #pragma unroll
            for (int half_idx = 0; half_idx < 2; half_idx++) {
                int r = half_idx ? r1 : r0;
                if (r >= g.M) continue;
                float a0 = half_idx ? acc[mi][nt][2] : acc[mi][nt][0];
                float a1 = half_idx ? acc[mi][nt][3] : acc[mi][nt][1];
                float e0 = 0.f, e1 = 0.f;
                if (g.E0) {
                    float2 t = *(const float2*)(g.E0 + (size_t)r * g.N + c);
                    e0 = t.x; e1 = t.y;
                }
                float v0 = (a0 + bias[nt][0] + e0) * g.outscale;
                float v1 = (a1 + bias[nt][1] + e1) * g.outscale;
                if (g.relu) { v0 = fmaxf(v0, 0.f); v1 = fmaxf(v1, 0.f); }
                if (g.out_half) {
                    *(__half2*)((__half*)g.C + (size_t)r * g.N + c) = __floats2half2_rn(v0, v1);
                } else {
                    *(float2*)((float*)g.C + (size_t)r * g.N + c) = make_float2(v0, v1);
                }
            }
        }
    }
}

// ---------------------------------------------------------------------------
// Host orchestration
// ---------------------------------------------------------------------------
static inline int ceil_div(int a, int b) { return (a + b - 1) / b; }

extern "C" void kernel_launch(void* const* d_in, const int* in_sizes, int n_in,
                              void* d_out, int out_size) {
    const float* x_tx   = (const float*)d_in[0];
    const float* x_user = (const float*)d_in[1];
    const float* x_merch= (const float*)d_in[2];
    const float* Wp     = (const float*)d_in[3];
    const float* bp     = (const float*)d_in[4];
    const float* Wl     = (const float*)d_in[5];
    const float* bl     = (const float*)d_in[6];
    const float* Wr     = (const float*)d_in[7];
    const float* Wc1    = (const float*)d_in[8];
    const float* bc1    = (const float*)d_in[9];
    const float* Wc2    = (const float*)d_in[10];
    const float* bc2    = (const float*)d_in[11];
    const float* Wv1    = (const float*)d_in[12];
    const float* bv1    = (const float*)d_in[13];
    const float* Wv2    = (const float*)d_in[14];
    const float* bv2    = (const float*)d_in[15];
    const int* e_ut_src = (const int*)d_in[16];
    const int* e_ut_dst = (const int*)d_in[17];
    const int* e_tm_src = (const int*)d_in[18];
    const int* e_tm_dst = (const int*)d_in[19];
    const int* e_mt_src = (const int*)d_in[20];
    const int* e_mt_dst = (const int*)d_in[21];
    const int* e_tu_src = (const int*)d_in[22];
    const int* e_tu_dst = (const int*)d_in[23];
    float* out = (float*)d_out;

    WS* ws = nullptr;
    cudaGetSymbolAddress((void**)&ws, g_ws);

    static cudaStream_t sB = nullptr, sC = nullptr;
    static cudaEvent_t ev[10];
    if (!sB) {
        cudaStreamCreateWithFlags(&sB, cudaStreamNonBlocking);
        cudaStreamCreateWithFlags(&sC, cudaStreamNonBlocking);
        for (int i = 0; i < 10; i++)
            cudaEventCreateWithFlags(&ev[i], cudaEventDisableTiming);
        cudaFuncSetAttribute(gemm_fp16, cudaFuncAttributeMaxDynamicSharedMemorySize,
                             GEMM_SMEM_BYTES);
    }
    cudaStream_t s0 = 0;
    cudaEvent_t evFork0 = ev[0], evPrep = ev[1], evCsr = ev[2], evProj = ev[3];
    cudaEvent_t evY0 = ev[4], evYm1 = ev[5], evGts1 = ev[6];

    const float* bl0_0 = bl + 0 * HDIM;
    const float* bl1_0 = bl + 1 * HDIM;
    const float* bl2_0 = bl + 2 * HDIM;
    const float* bl3_0 = bl + 3 * HDIM;
    const float* bl0_1 = bl + 4 * HDIM;
    const float* bl2_1 = bl + 6 * HDIM;

    cudaEventRecord(evFork0, s0);
    cudaStreamWaitEvent(sB, evFork0, 0);
    cudaStreamWaitEvent(sC, evFork0, 0);

    // ======== s0: x_tx fp16 convert ========
    conv_x<<<ceil_div(NTX * FIN / 4, 256), 256, 0, s0>>>(x_tx, ws->xtx_h, NTX * FIN / 4);

    // ======== sC: weight + activation prep ========
    int cg = ceil_div(HDIM * HDIM, 256);
    conv_all<<<dim3(cg, 9), 256, 0, sC>>>(Wl, Wr, Wp);
    prep_wsum_h<<<dim3(cg, 2), 256, 0, sC>>>(Wr);
    prep_wcat_h<<<cg, 256, 0, sC>>>(Wc1, Wv1, bc1, bv1, Wc2, Wv2);
    conv_x<<<ceil_div(NUSER * HDIM / 4, 256), 256, 0, sC>>>(x_user, ws->xu_h, NUSER * HDIM / 4);
    conv_x<<<ceil_div(NMERCH * HDIM / 4, 256), 256, 0, sC>>>(x_merch, ws->xm_h, NMERCH * HDIM / 4);
    cudaEventRecord(evPrep, sC);

    // ======== sB: CSR build ========
    cudaMemsetAsync(ws->deg,    0, sizeof(ws->deg),    sB);
    cudaMemsetAsync(ws->cursor, 0, sizeof(ws->cursor), sB);
    build_count<<<dim3(ceil_div(NEDGE, 256), 4), 256, 0, sB>>>(e_ut_dst, e_tm_dst, e_mt_dst, e_tu_dst);
    scan4<<<4, 1024, 0, sB>>>(NTX, NMERCH, NTX, NUSER);
    build_fill<<<dim3(ceil_div(NEDGE, 256), 4), 256, 0, sB>>>(e_ut_src, e_ut_dst, e_tm_src, e_tm_dst,
                                                              e_mt_src, e_mt_dst, e_tu_src, e_tu_dst);
    cudaEventRecord(evCsr, sB);

    // ======== s0: proj ========
    cudaStreamWaitEvent(s0, evPrep, 0);
    {
        GemmArgs a = {};
        a.A[0] = ws->xtx_h; a.W[0] = ws->wp_h; a.b0 = bp;
        a.C = ws->xth[0]; a.M = NTX; a.N = HDIM; a.nseg = 1; a.segK = FIN;
        a.outscale = 1.0f; a.relu = 0; a.out_half = 1;
        gemm_fp16<<<dim3(ceil_div(NTX, BM), HDIM / BN), 256, GEMM_SMEM_BYTES, s0>>>(a);
    }
    cudaEventRecord(evProj, s0);

    // ======== sB (cont): mm0 -> xm1 -> ym1 ========
    cudaStreamWaitEvent(sB, evProj, 0);
    seg_mean_h<<<ceil_div(NMERCH * 32, 256), 256, 0, sB>>>(ws->xth[0], 1, ws->mmh, NMERCH);
    {
        GemmArgs a = {};
        a.A[0] = ws->mmh;  a.W[0] = ws->wl1h;
        a.A[1] = ws->xm_h; a.W[1] = ws->wr1h;
        a.b0 = bl1_0;
        a.C = ws->xm1h; a.M = NMERCH; a.N = HDIM; a.nseg = 2; a.segK = HDIM;
        a.outscale = 1.0f; a.relu = 1; a.out_half = 1;
        gemm_fp16<<<dim3(ceil_div(NMERCH, BM), HDIM / BN), 256, GEMM_SMEM_BYTES, sB>>>(a);
    }
    {
        GemmArgs a = {};
        a.A[0] = ws->xm1h; a.W[0] = ws->wl2h[1];
        a.C = ws->ymh[1]; a.M = NMERCH; a.N = HDIM; a.nseg = 1; a.segK = HDIM;
        a.outscale = 1.0f; a.relu = 0; a.out_half = 1;
        gemm_fp16<<<dim3(ceil_div(NMERCH, BM), HDIM / BN), 256, GEMM_SMEM_BYTES, sB>>>(a);
    }
    cudaEventRecord(evYm1, sB);

    // ======== sC (cont): yu0/ym0 (fp16 out), mu0 -> xu1 -> yu1 -> dual1 ========
    {
        GemmArgs a = {};
        a.A[0] = ws->xu_h; a.W[0] = ws->wl0h[0];
        a.C = ws->yuh[0]; a.M = NUSER; a.N = HDIM; a.nseg = 1; a.segK = HDIM;
        a.outscale = 1.0f; a.relu = 0; a.out_half = 1;
        gemm_fp16<<<dim3(ceil_div(NUSER, BM), HDIM / BN), 256, GEMM_SMEM_BYTES, sC>>>(a);
    }
    {
        GemmArgs a = {};
        a.A[0] = ws->xm_h; a.W[0] = ws->wl2h[0];
        a.C = ws->ymh[0]; a.M = NMERCH; a.N = HDIM; a.nseg = 1; a.segK = HDIM;
        a.outscale = 1.0f; a.relu = 0; a.out_half = 1;
        gemm_fp16<<<dim3(ceil_div(NMERCH, BM), HDIM / BN), 256, GEMM_SMEM_BYTES, sC>>>(a);
    }
    cudaEventRecord(evY0, sC);
    cudaStreamWaitEvent(sC, evCsr, 0);
    cudaStreamWaitEvent(sC, evProj, 0);
    seg_mean_h<<<ceil_div(NUSER * 32, 256), 256, 0, sC>>>(ws->xth[0], 3, ws->muh, NUSER);
    {
        GemmArgs a = {};
        a.A[0] = ws->muh;  a.W[0] = ws->wl3h;
        a.A[1] = ws->xu_h; a.W[1] = ws->wr3h;
        a.b0 = bl3_0;
        a.C = ws->xu1h; a.M = NUSER; a.N = HDIM; a.nseg = 2; a.segK = HDIM;
        a.outscale = 1.0f; a.relu = 1; a.out_half = 1;
        gemm_fp16<<<dim3(ceil_div(NUSER, BM), HDIM / BN), 256, GEMM_SMEM_BYTES, sC>>>(a);
    }
    {
        GemmArgs a = {};
        a.A[0] = ws->xu1h; a.W[0] = ws->wl0h[1];
        a.C = ws->yuh[1]; a.M = NUSER; a.N = HDIM; a.nseg = 1; a.segK = HDIM;
        a.outscale = 1.0f; a.relu = 0; a.out_half = 1;
        gemm_fp16<<<dim3(ceil_div(NUSER, BM), HDIM / BN), 256, GEMM_SMEM_BYTES, sC>>>(a);
    }
    cudaStreamWaitEvent(sC, evYm1, 0);
    seg_mean_dual_h<<<ceil_div(NTX * 32, 256), 256, 0, sC>>>(ws->yuh[1], ws->ymh[1], ws->gts[1]);
    cudaEventRecord(evGts1, sC);

    // ======== s0 (cont): dual0 -> xtL0 -> xtL1 -> fused head ========
    cudaStreamWaitEvent(s0, evY0, 0);
    cudaStreamWaitEvent(s0, evCsr, 0);
    seg_mean_dual_h<<<ceil_div(NTX * 32, 256), 256, 0, s0>>>(ws->yuh[0], ws->ymh[0], ws->gts[0]);
    {
        GemmArgs a = {};
        a.A[0] = ws->xth[0]; a.W[0] = ws->wsum_h[0];
        a.b0 = bl0_0; a.b1 = bl2_0;
        a.E0 = ws->gts[0];
        a.C = ws->xth[1]; a.M = NTX; a.N = HDIM; a.nseg = 1; a.segK = HDIM;
        a.outscale = 0.5f; a.relu = 1; a.out_half = 1;
        gemm_fp16<<<dim3(ceil_div(NTX, BM), HDIM / BN), 256, GEMM_SMEM_BYTES, s0>>>(a);
    }
    cudaStreamWaitEvent(s0, evGts1, 0);
    {
        GemmArgs a = {};
        a.A[0] = ws->xth[1]; a.W[0] = ws->wsum_h[1];
        a.b0 = bl0_1; a.b1 = bl2_1;
        a.E0 = ws->gts[1];
        a.C = ws->xth[0]; a.M = NTX; a.N = HDIM; a.nseg = 1; a.segK = HDIM;
        a.outscale = 0.5f; a.relu = 1; a.out_half = 1;
        gemm_fp16<<<dim3(ceil_div(NTX, BM), HDIM / BN), 256, GEMM_SMEM_BYTES, s0>>>(a);
    }
    {
        GemmArgs a = {};
        a.A[0] = ws->xth[0]; a.W[0] = ws->wcat_h; a.b0 = ws->bcat;
        a.C = out; a.M = NTX; a.N = HDIM; a.nseg = 1; a.segK = HDIM;
        a.outscale = 1.0f; a.relu = 1;
        a.headmode = 1; a.w2 = ws->w2cat; a.b2c = bc2; a.b2v = bv2;
        gemm_fp16<<<dim3(ceil_div(NTX, BM), HDIM / BN), 256, GEMM_SMEM_BYTES, s0>>>(a);
    }
}

// round 13
// speedup vs baseline: 1.2274x; 1.0268x over previous
#include <cuda_runtime.h>
#include <cuda_fp16.h>
#include <cstdint>

#define NTX    100000
#define NUSER  20000
#define NMERCH 5000
#define NEDGE  400000
#define HDIM   256
#define HHALF  128
#define FIN    32

// ---------------------------------------------------------------------------
// Workspace (single __device__ global; no allocations allowed)
// ---------------------------------------------------------------------------
struct WS {
    // fp16 activations
    __half xth[2][NTX * HDIM];
    __half xtx_h [NTX * FIN];
    __half xu_h  [NUSER * HDIM];
    __half xm_h  [NMERCH * HDIM];
    __half mmh [NMERCH * HDIM];
    __half muh [NUSER * HDIM];
    __half xm1h[NMERCH * HDIM];
    __half xu1h[NUSER * HDIM];
    __half yuh [2][NUSER * HDIM];    // xu@Wl0 per layer (fp16, gather source)
    __half ymh [2][NMERCH * HDIM];   // xm@Wl2 per layer (fp16, gather source)
    // fp32 (epilogue addend — precision-critical)
    float gts[2][NTX * HDIM];
    float bcat[HDIM];
    float w2cat[HDIM];
    // fp16 weights, transposed to [n][k]
    __half wp_h  [HDIM * FIN];
    __half wl0h[2][HDIM * HDIM];
    __half wl2h[2][HDIM * HDIM];
    __half wl1h  [HDIM * HDIM];
    __half wr1h  [HDIM * HDIM];
    __half wl3h  [HDIM * HDIM];
    __half wr3h  [HDIM * HDIM];
    __half wsum_h[2][HDIM * HDIM];
    __half wcat_h[HDIM * HDIM];
    int deg   [4][NTX];
    int cursor[4][NTX];
    int rowptr[4][NTX + 1];
    int perm  [4][NEDGE];
};
__device__ WS g_ws;

// relations: 0 = user->tx, 1 = tx->merch, 2 = merch->tx, 3 = tx->user
// ---------------------------------------------------------------------------
// CSR build
// ---------------------------------------------------------------------------
__global__ void build_count(const int* __restrict__ d0, const int* __restrict__ d1,
                            const int* __restrict__ d2, const int* __restrict__ d3) {
    int i = blockIdx.x * blockDim.x + threadIdx.x;
    if (i >= NEDGE) return;
    int rel = blockIdx.y;
    const int* d = (rel == 0) ? d0 : (rel == 1) ? d1 : (rel == 2) ? d2 : d3;
    atomicAdd(&g_ws.deg[rel][d[i]], 1);
}

__global__ void scan4(int n0, int n1, int n2, int n3) {
    int rel = blockIdx.x;
    int n = (rel == 0) ? n0 : (rel == 1) ? n1 : (rel == 2) ? n2 : n3;
    const int* deg = g_ws.deg[rel];
    int* rp = g_ws.rowptr[rel];
    __shared__ int wsum[32];
    __shared__ int s_carry;
    int tid = threadIdx.x, lane = tid & 31, wid = tid >> 5;
    if (tid == 0) s_carry = 0;
    __syncthreads();
    for (int base = 0; base < n; base += 1024) {
        int i = base + tid;
        int v = (i < n) ? deg[i] : 0;
        int x = v;
        #pragma unroll
        for (int off = 1; off < 32; off <<= 1) {
            int u = __shfl_up_sync(0xffffffffu, x, off);
            if (lane >= off) x += u;
        }
        if (lane == 31) wsum[wid] = x;
        __syncthreads();
        if (wid == 0) {
            int w = wsum[lane];
            int y = w;
            #pragma unroll
            for (int off = 1; off < 32; off <<= 1) {
                int u = __shfl_up_sync(0xffffffffu, y, off);
                if (lane >= off) y += u;
            }
            wsum[lane] = y - w;
        }
        __syncthreads();
        int incl = x + wsum[wid];
        int c = s_carry;
        __syncthreads();
        if (i < n) rp[i] = c + incl - v;
        if (tid == 1023) s_carry = c + incl;
        __syncthreads();
    }
    if (tid == 0) rp[n] = s_carry;
}

__global__ void build_fill(const int* __restrict__ s0, const int* __restrict__ d0,
                           const int* __restrict__ s1, const int* __restrict__ d1,
                           const int* __restrict__ s2, const int* __restrict__ d2,
                           const int* __restrict__ s3, const int* __restrict__ d3) {
    int i = blockIdx.x * blockDim.x + threadIdx.x;
    if (i >= NEDGE) return;
    int rel = blockIdx.y;
    const int* s = (rel == 0) ? s0 : (rel == 1) ? s1 : (rel == 2) ? s2 : s3;
    const int* d = (rel == 0) ? d0 : (rel == 1) ? d1 : (rel == 2) ? d2 : d3;
    int dst = d[i];
    int pos = g_ws.rowptr[rel][dst] + atomicAdd(&g_ws.cursor[rel][dst], 1);
    g_ws.perm[rel][pos] = s[i];
}

// ---------------------------------------------------------------------------
// Prep kernels
// ---------------------------------------------------------------------------
__global__ void conv_all(const float* __restrict__ Wl, const float* __restrict__ Wr,
                         const float* __restrict__ Wp) {
    int m = blockIdx.y;
    int i = blockIdx.x * blockDim.x + threadIdx.x;
    if (m == 0) {
        if (i >= HDIM * FIN) return;
        int n = i / FIN, k = i % FIN;
        g_ws.wp_h[i] = __float2half(Wp[k * HDIM + n]);
        return;
    }
    if (i >= HDIM * HDIM) return;
    const float* src;
    __half* dst;
    const size_t S = (size_t)HDIM * HDIM;
    switch (m) {
        case 1: src = Wl + 0 * S; dst = g_ws.wl0h[0]; break;
        case 2: src = Wl + 2 * S; dst = g_ws.wl2h[0]; break;
        case 3: src = Wl + 4 * S; dst = g_ws.wl0h[1]; break;
        case 4: src = Wl + 6 * S; dst = g_ws.wl2h[1]; break;
        case 5: src = Wl + 1 * S; dst = g_ws.wl1h;    break;
        case 6: src = Wr + 1 * S; dst = g_ws.wr1h;    break;
        case 7: src = Wl + 3 * S; dst = g_ws.wl3h;    break;
        default: src = Wr + 3 * S; dst = g_ws.wr3h;   break;
    }
    int n = i >> 8, k = i & 255;
    dst[i] = __float2half(src[k * HDIM + n]);
}

__global__ void prep_wsum_h(const float* __restrict__ Wr) {
    int i = blockIdx.x * blockDim.x + threadIdx.x;
    if (i >= HDIM * HDIM) return;
    int l = blockIdx.y;
    int n = i >> 8, k = i & 255;
    const float* Wr0 = Wr + ((size_t)(l * 4 + 0)) * HDIM * HDIM;
    const float* Wr2 = Wr + ((size_t)(l * 4 + 2)) * HDIM * HDIM;
    g_ws.wsum_h[l][i] = __float2half(Wr0[k * HDIM + n] + Wr2[k * HDIM + n]);
}

__global__ void prep_wcat_h(const float* __restrict__ Wc1, const float* __restrict__ Wv1,
                            const float* __restrict__ bc1, const float* __restrict__ bv1,
                            const float* __restrict__ Wc2, const float* __restrict__ Wv2) {
    int i = blockIdx.x * blockDim.x + threadIdx.x;
    if (i < HDIM * HDIM) {
        int n = i >> 8, k = i & 255;
        float v = (n < HHALF) ? Wc1[k * HHALF + n] : Wv1[k * HHALF + (n - HHALF)];
        g_ws.wcat_h[i] = __float2half(v);
    }
    if (i < HDIM) {
        g_ws.bcat[i]  = (i < HHALF) ? bc1[i] : bv1[i - HHALF];
        g_ws.w2cat[i] = (i < HHALF) ? Wc2[i] : Wv2[i - HHALF];
    }
}

__global__ void conv_x(const float* __restrict__ x, __half* __restrict__ y, int n4) {
    int i = blockIdx.x * blockDim.x + threadIdx.x;
    if (i >= n4) return;
    float4 v = ((const float4*)x)[i];
    ((__half2*)y)[i * 2 + 0] = __floats2half2_rn(v.x, v.y);
    ((__half2*)y)[i * 2 + 1] = __floats2half2_rn(v.z, v.w);
}

// ---------------------------------------------------------------------------
// Segment-mean kernels (edge loops unrolled x2 for MLP; accumulation order
// identical to sequential version)
// ---------------------------------------------------------------------------
__device__ __forceinline__ void acc_row_h(const __half* __restrict__ src, int s,
                                          int lane, float* acc) {
    uint4 v = ((const uint4*)(src + (size_t)s * HDIM))[lane];
    const __half2* h = (const __half2*)&v;
    #pragma unroll
    for (int j = 0; j < 4; j++) {
        float2 f = __half22float2(h[j]);
        acc[j * 2 + 0] += f.x;
        acc[j * 2 + 1] += f.y;
    }
}

// half in -> half out (fp32 accumulation)
__global__ void seg_mean_h(const __half* __restrict__ xsrc, int rel,
                           __half* __restrict__ outm, int n_dst) {
    int w = (blockIdx.x * blockDim.x + threadIdx.x) >> 5;
    int lane = threadIdx.x & 31;
    if (w >= n_dst) return;
    const int* __restrict__ rp = g_ws.rowptr[rel];
    const int* __restrict__ pm = g_ws.perm[rel];
    int beg = rp[w], end = rp[w + 1];
    float acc[8];
    #pragma unroll
    for (int j = 0; j < 8; j++) acc[j] = 0.f;
    int e = beg;
    for (; e + 1 < end; e += 2) {
        int s0 = pm[e], s1 = pm[e + 1];
        acc_row_h(xsrc, s0, lane, acc);
        acc_row_h(xsrc, s1, lane, acc);
    }
    if (e < end) acc_row_h(xsrc, pm[e], lane, acc);
    float inv = 1.0f / (float)max(end - beg, 1);
    uint4 o;
    __half2* oh = (__half2*)&o;
    #pragma unroll
    for (int j = 0; j < 4; j++)
        oh[j] = __floats2half2_rn(acc[j * 2] * inv, acc[j * 2 + 1] * inv);
    ((uint4*)(outm + (size_t)w * HDIM))[lane] = o;
}

// fp16 dual gather: gts = mean_rel0(ya) + mean_rel2(yb), fp32 accumulation+output
__global__ void seg_mean_dual_h(const __half* __restrict__ ya, const __half* __restrict__ yb,
                                float* __restrict__ outm) {
    int w = (blockIdx.x * blockDim.x + threadIdx.x) >> 5;
    int lane = threadIdx.x & 31;
    if (w >= NTX) return;

    float r[8];
    #pragma unroll
    for (int j = 0; j < 8; j++) r[j] = 0.f;

    {
        const int* __restrict__ rp = g_ws.rowptr[0];
        const int* __restrict__ pm = g_ws.perm[0];
        int beg = rp[w], end = rp[w + 1];
        float a[8];
        #pragma unroll
        for (int j = 0; j < 8; j++) a[j] = 0.f;
        int e = beg;
        for (; e + 1 < end; e += 2) {
            int s0 = pm[e], s1 = pm[e + 1];
            acc_row_h(ya, s0, lane, a);
            acc_row_h(ya, s1, lane, a);
        }
        if (e < end) acc_row_h(ya, pm[e], lane, a);
        float inv = 1.0f / (float)max(end - beg, 1);
        #pragma unroll
        for (int j = 0; j < 8; j++) r[j] += a[j] * inv;
    }
    {
        const int* __restrict__ rp = g_ws.rowptr[2];
        const int* __restrict__ pm = g_ws.perm[2];
        int beg = rp[w], end = rp[w + 1];
        float a[8];
        #pragma unroll
        for (int j = 0; j < 8; j++) a[j] = 0.f;
        int e = beg;
        for (; e + 1 < end; e += 2) {
            int s0 = pm[e], s1 = pm[e + 1];
            acc_row_h(yb, s0, lane, a);
            acc_row_h(yb, s1, lane, a);
        }
        if (e < end) acc_row_h(yb, pm[e], lane, a);
        float inv = 1.0f / (float)max(end - beg, 1);
        #pragma unroll
        for (int j = 0; j < 8; j++) r[j] += a[j] * inv;
    }

    float* o = outm + (size_t)w * HDIM + lane * 8;
    *(float4*)(o + 0) = make_float4(r[0], r[1], r[2], r[3]);
    *(float4*)(o + 4) = make_float4(r[4], r[5], r[6], r[7]);
}

// ---------------------------------------------------------------------------
// Fused GEMM: fp16 A/W, fp32 acc, cp.async double-buffered; fp32/fp16 out,
// optional fp32 E0 add, optional fused head.
// ---------------------------------------------------------------------------
#define BM 128
#define BN 128
#define BK 32
#define ASTH 40
#define WPAD 56
#define A_STAGE_BYTES (BM * ASTH * 2)
#define W_STAGE_BYTES (BN * WPAD * 2)
#define STAGE_BYTES (A_STAGE_BYTES + W_STAGE_BYTES)
#define GEMM_SMEM_BYTES (2 * STAGE_BYTES)

struct GemmArgs {
    const __half* A[2];
    const __half* W[2];
    const float* b0;
    const float* b1;
    const float* E0;
    void* C;
    int M, N, nseg, segK;
    float outscale;
    int relu;
    int out_half;
    int headmode;
    const float* w2;
    const float* b2c;
    const float* b2v;
};

__device__ __forceinline__ void cp_async16(uint32_t smem_addr, const void* gptr, int src_bytes) {
    asm volatile("cp.async.cg.shared.global [%0], [%1], 16, %2;"
                 :: "r"(smem_addr), "l"(gptr), "r"(src_bytes));
}
__device__ __forceinline__ void cp_commit() {
    asm volatile("cp.async.commit_group;");
}
template <int N>
__device__ __forceinline__ void cp_wait() {
    asm volatile("cp.async.wait_group %0;" :: "n"(N));
}

__global__ void __launch_bounds__(256, 2) gemm_fp16(GemmArgs g) {
    extern __shared__ char smem_c[];

    int tid = threadIdx.x;
    int lane = tid & 31;
    int warp = tid >> 5;
    int wm = (warp & 3) * 32;
    int wn = (warp >> 2) * 64;
    int grp = lane >> 2;
    int tg  = lane & 3;

    int m0 = blockIdx.x * BM, n0 = blockIdx.y * BN;

    int ld_row = tid >> 1;
    int cb = (tid & 1) * 2;

    int a_grow = m0 + ld_row;
    bool a_ok = (a_grow < g.M);

    uint32_t smem_base = (uint32_t)__cvta_generic_to_shared(smem_c);
    int ktiles = g.nseg * g.segK / BK;

    auto issue_tile = [&](int kt, int st) {
        int k0 = kt * BK;
        int seg = k0 / g.segK;
        int koff = k0 - seg * g.segK;
        const __half* A = g.A[seg];
        const __half* W = g.W[seg];

        uint32_t a_s = smem_base + st * STAGE_BYTES + ld_row * (ASTH * 2);
        const __half* a_g = A + (size_t)a_grow * g.segK + koff;
        int a_sz = a_ok ? 16 : 0;
        #pragma unroll
        for (int c = 0; c < 2; c++)
            cp_async16(a_s + (cb + c) * 16, a_g + (cb + c) * 8, a_sz);

        uint32_t w_s = smem_base + st * STAGE_BYTES + A_STAGE_BYTES + ld_row * (WPAD * 2);
        const __half* w_g = W + (size_t)(n0 + ld_row) * g.segK + koff;
        #pragma unroll
        for (int c = 0; c < 2; c++)
            cp_async16(w_s + (cb + c) * 16, w_g + (cb + c) * 8, 16);

        cp_commit();
    };

    float acc[2][8][4];
    #pragma unroll
    for (int i = 0; i < 2; i++)
        #pragma unroll
        for (int j = 0; j < 8; j++)
            #pragma unroll
            for (int c = 0; c < 4; c++) acc[i][j][c] = 0.f;

    issue_tile(0, 0);

    for (int kt = 0; kt < ktiles; kt++) {
        int st = kt & 1;
        if (kt + 1 < ktiles) {
            issue_tile(kt + 1, (kt + 1) & 1);
            cp_wait<1>();
        } else {
            cp_wait<0>();
        }
        __syncthreads();

        const __half* As = (const __half*)(smem_c + st * STAGE_BYTES);
        const __half* Ws = (const __half*)(smem_c + st * STAGE_BYTES + A_STAGE_BYTES);

        #pragma unroll
        for (int ks = 0; ks < BK / 16; ks++) {
            int kb = ks * 16;
            uint32_t afr[2][4];
            #pragma unroll
            for (int mi = 0; mi < 2; mi++) {
                int r = wm + mi * 16 + grp;
                afr[mi][0] = *(const uint32_t*)(As + r * ASTH + kb + 2 * tg);
                afr[mi][1] = *(const uint32_t*)(As + (r + 8) * ASTH + kb + 2 * tg);
                afr[mi][2] = *(const uint32_t*)(As + r * ASTH + kb + 8 + 2 * tg);
                afr[mi][3] = *(const uint32_t*)(As + (r + 8) * ASTH + kb + 8 + 2 * tg);
            }
            uint32_t bfr[8][2];
            #pragma unroll
            for (int nt = 0; nt < 8; nt++) {
                int nb = wn + nt * 8 + grp;
                bfr[nt][0] = *(const uint32_t*)(Ws + nb * WPAD + kb + 2 * tg);
                bfr[nt][1] = *(const uint32_t*)(Ws + nb * WPAD + kb + 8 + 2 * tg);
            }
            #pragma unroll
            for (int mi = 0; mi < 2; mi++) {
                #pragma unroll
                for (int nt = 0; nt < 8; nt++) {
                    asm volatile(
                        "mma.sync.aligned.m16n8k16.row.col.f32.f16.f16.f32 "
                        "{%0,%1,%2,%3}, {%4,%5,%6,%7}, {%8,%9}, {%0,%1,%2,%3};"
                        : "+f"(acc[mi][nt][0]), "+f"(acc[mi][nt][1]),
                          "+f"(acc[mi][nt][2]), "+f"(acc[mi][nt][3])
                        : "r"(afr[mi][0]), "r"(afr[mi][1]),
                          "r"(afr[mi][2]), "r"(afr[mi][3]),
                          "r"(bfr[nt][0]), "r"(bfr[nt][1]));
                }
            }
        }
        __syncthreads();
    }

    float bias[8][2];
    #pragma unroll
    for (int nt = 0; nt < 8; nt++) {
        int c = n0 + wn + nt * 8 + tg * 2;
        float b0v = 0.f, b1v = 0.f;
        if (g.b0) { b0v = g.b0[c] + (g.b1 ? g.b1[c] : 0.f); }
        if (g.b0) { b1v = g.b0[c + 1] + (g.b1 ? g.b1[c + 1] : 0.f); }
        bias[nt][0] = b0v;
        bias[nt][1] = b1v;
    }

    if (g.headmode) {
        float* red = (float*)smem_c;
        for (int i = tid; i < BM; i += 256) red[i] = 0.f;
        __syncthreads();
        #pragma unroll
        for (int mi = 0; mi < 2; mi++) {
            float p0 = 0.f, p1 = 0.f;
            #pragma unroll
            for (int nt = 0; nt < 8; nt++) {
                int c = n0 + wn + nt * 8 + tg * 2;
                float w20 = g.w2[c], w21 = g.w2[c + 1];
                float v00 = fmaxf(acc[mi][nt][0] + bias[nt][0], 0.f);
                float v01 = fmaxf(acc[mi][nt][1] + bias[nt][1], 0.f);
                float v10 = fmaxf(acc[mi][nt][2] + bias[nt][0], 0.f);
                float v11 = fmaxf(acc[mi][nt][3] + bias[nt][1], 0.f);
                p0 += v00 * w20 + v01 * w21;
                p1 += v10 * w20 + v11 * w21;
            }
            atomicAdd(&red[wm + mi * 16 + grp], p0);
            atomicAdd(&red[wm + mi * 16 + grp + 8], p1);
        }
        __syncthreads();
        if (tid < BM) {
            int row = m0 + tid;
            if (row < g.M) {
                int off = (n0 >= HHALF) ? NTX : 0;
                float b2 = (n0 >= HHALF) ? g.b2v[0] : g.b2c[0];
                ((float*)g.C)[off + row] = red[tid] + b2;
            }
        }
        return;
    }

    #pragma unroll
    for (int mi = 0; mi < 2; mi++) {
        int r0 = m0 + wm + mi * 16 + grp;
        int r1 = r0 + 8;
        #pragma unroll
        for (int nt = 0; nt < 8; nt++) {
            int c = n0 + wn + nt * 8 + tg * 2;
            #pragma unroll
            for (int half_idx = 0; half_idx < 2; half_idx++) {
                int r = half_idx ? r1 : r0;
                if (r >= g.M) continue;
                float a0 = half_idx ? acc[mi][nt][2] : acc[mi][nt][0];
                float a1 = half_idx ? acc[mi][nt][3] : acc[mi][nt][1];
                float e0 = 0.f, e1 = 0.f;
                if (g.E0) {
                    float2 t = *(const float2*)(g.E0 + (size_t)r * g.N + c);
                    e0 = t.x; e1 = t.y;
                }
                float v0 = (a0 + bias[nt][0] + e0) * g.outscale;
                float v1 = (a1 + bias[nt][1] + e1) * g.outscale;
                if (g.relu) { v0 = fmaxf(v0, 0.f); v1 = fmaxf(v1, 0.f); }
                if (g.out_half) {
                    *(__half2*)((__half*)g.C + (size_t)r * g.N + c) = __floats2half2_rn(v0, v1);
                } else {
                    *(float2*)((float*)g.C + (size_t)r * g.N + c) = make_float2(v0, v1);
                }
            }
        }
    }
}

// ---------------------------------------------------------------------------
// Host orchestration: 4-stream schedule, dual0 fully concurrent with proj
// ---------------------------------------------------------------------------
static inline int ceil_div(int a, int b) { return (a + b - 1) / b; }

extern "C" void kernel_launch(void* const* d_in, const int* in_sizes, int n_in,
                              void* d_out, int out_size) {
    const float* x_tx   = (const float*)d_in[0];
    const float* x_user = (const float*)d_in[1];
    const float* x_merch= (const float*)d_in[2];
    const float* Wp     = (const float*)d_in[3];
    const float* bp     = (const float*)d_in[4];
    const float* Wl     = (const float*)d_in[5];
    const float* bl     = (const float*)d_in[6];
    const float* Wr     = (const float*)d_in[7];
    const float* Wc1    = (const float*)d_in[8];
    const float* bc1    = (const float*)d_in[9];
    const float* Wc2    = (const float*)d_in[10];
    const float* bc2    = (const float*)d_in[11];
    const float* Wv1    = (const float*)d_in[12];
    const float* bv1    = (const float*)d_in[13];
    const float* Wv2    = (const float*)d_in[14];
    const float* bv2    = (const float*)d_in[15];
    const int* e_ut_src = (const int*)d_in[16];
    const int* e_ut_dst = (const int*)d_in[17];
    const int* e_tm_src = (const int*)d_in[18];
    const int* e_tm_dst = (const int*)d_in[19];
    const int* e_mt_src = (const int*)d_in[20];
    const int* e_mt_dst = (const int*)d_in[21];
    const int* e_tu_src = (const int*)d_in[22];
    const int* e_tu_dst = (const int*)d_in[23];
    float* out = (float*)d_out;

    WS* ws = nullptr;
    cudaGetSymbolAddress((void**)&ws, g_ws);

    static cudaStream_t sB = nullptr, sC = nullptr, sD = nullptr;
    static cudaEvent_t ev[10];
    if (!sB) {
        cudaStreamCreateWithFlags(&sB, cudaStreamNonBlocking);
        cudaStreamCreateWithFlags(&sC, cudaStreamNonBlocking);
        cudaStreamCreateWithFlags(&sD, cudaStreamNonBlocking);
        for (int i = 0; i < 10; i++)
            cudaEventCreateWithFlags(&ev[i], cudaEventDisableTiming);
        cudaFuncSetAttribute(gemm_fp16, cudaFuncAttributeMaxDynamicSharedMemorySize,
                             GEMM_SMEM_BYTES);
    }
    cudaStream_t s0 = 0;
    cudaEvent_t evFork0 = ev[0], evPrep = ev[1], evCsr = ev[2], evProj = ev[3];
    cudaEvent_t evY0 = ev[4], evYm1 = ev[5], evGts1 = ev[6], evGts0 = ev[7];

    const float* bl0_0 = bl + 0 * HDIM;
    const float* bl1_0 = bl + 1 * HDIM;
    const float* bl2_0 = bl + 2 * HDIM;
    const float* bl3_0 = bl + 3 * HDIM;
    const float* bl0_1 = bl + 4 * HDIM;
    const float* bl2_1 = bl + 6 * HDIM;

    cudaEventRecord(evFork0, s0);
    cudaStreamWaitEvent(sB, evFork0, 0);
    cudaStreamWaitEvent(sC, evFork0, 0);
    cudaStreamWaitEvent(sD, evFork0, 0);

    // ======== s0: x_tx fp16 convert ========
    conv_x<<<ceil_div(NTX * FIN / 4, 256), 256, 0, s0>>>(x_tx, ws->xtx_h, NTX * FIN / 4);

    // ======== sC: weight + activation prep, then yu0/ym0 ========
    int cg = ceil_div(HDIM * HDIM, 256);
    conv_all<<<dim3(cg, 9), 256, 0, sC>>>(Wl, Wr, Wp);
    prep_wsum_h<<<dim3(cg, 2), 256, 0, sC>>>(Wr);
    prep_wcat_h<<<cg, 256, 0, sC>>>(Wc1, Wv1, bc1, bv1, Wc2, Wv2);
    conv_x<<<ceil_div(NUSER * HDIM / 4, 256), 256, 0, sC>>>(x_user, ws->xu_h, NUSER * HDIM / 4);
    conv_x<<<ceil_div(NMERCH * HDIM / 4, 256), 256, 0, sC>>>(x_merch, ws->xm_h, NMERCH * HDIM / 4);
    cudaEventRecord(evPrep, sC);
    {
        GemmArgs a = {};
        a.A[0] = ws->xu_h; a.W[0] = ws->wl0h[0];
        a.C = ws->yuh[0]; a.M = NUSER; a.N = HDIM; a.nseg = 1; a.segK = HDIM;
        a.outscale = 1.0f; a.relu = 0; a.out_half = 1;
        gemm_fp16<<<dim3(ceil_div(NUSER, BM), HDIM / BN), 256, GEMM_SMEM_BYTES, sC>>>(a);
    }
    {
        GemmArgs a = {};
        a.A[0] = ws->xm_h; a.W[0] = ws->wl2h[0];
        a.C = ws->ymh[0]; a.M = NMERCH; a.N = HDIM; a.nseg = 1; a.segK = HDIM;
        a.outscale = 1.0f; a.relu = 0; a.out_half = 1;
        gemm_fp16<<<dim3(ceil_div(NMERCH, BM), HDIM / BN), 256, GEMM_SMEM_BYTES, sC>>>(a);
    }
    cudaEventRecord(evY0, sC);

    // ======== sB: CSR build ========
    cudaMemsetAsync(ws->deg,    0, sizeof(ws->deg),    sB);
    cudaMemsetAsync(ws->cursor, 0, sizeof(ws->cursor), sB);
    build_count<<<dim3(ceil_div(NEDGE, 256), 4), 256, 0, sB>>>(e_ut_dst, e_tm_dst, e_mt_dst, e_tu_dst);
    scan4<<<4, 1024, 0, sB>>>(NTX, NMERCH, NTX, NUSER);
    build_fill<<<dim3(ceil_div(NEDGE, 256), 4), 256, 0, sB>>>(e_ut_src, e_ut_dst, e_tm_src, e_tm_dst,
                                                              e_mt_src, e_mt_dst, e_tu_src, e_tu_dst);
    cudaEventRecord(evCsr, sB);

    // ======== sD: dual0 (concurrent with proj) ========
    cudaStreamWaitEvent(sD, evY0, 0);
    cudaStreamWaitEvent(sD, evCsr, 0);
    seg_mean_dual_h<<<ceil_div(NTX * 32, 256), 256, 0, sD>>>(ws->yuh[0], ws->ymh[0], ws->gts[0]);
    cudaEventRecord(evGts0, sD);

    // ======== s0: proj ========
    cudaStreamWaitEvent(s0, evPrep, 0);
    {
        GemmArgs a = {};
        a.A[0] = ws->xtx_h; a.W[0] = ws->wp_h; a.b0 = bp;
        a.C = ws->xth[0]; a.M = NTX; a.N = HDIM; a.nseg = 1; a.segK = FIN;
        a.outscale = 1.0f; a.relu = 0; a.out_half = 1;
        gemm_fp16<<<dim3(ceil_div(NTX, BM), HDIM / BN), 256, GEMM_SMEM_BYTES, s0>>>(a);
    }
    cudaEventRecord(evProj, s0);

    // ======== sB (cont): mm0 -> xm1 -> ym1 ========
    cudaStreamWaitEvent(sB, evProj, 0);
    seg_mean_h<<<ceil_div(NMERCH * 32, 256), 256, 0, sB>>>(ws->xth[0], 1, ws->mmh, NMERCH);
    {
        GemmArgs a = {};
        a.A[0] = ws->mmh;  a.W[0] = ws->wl1h;
        a.A[1] = ws->xm_h; a.W[1] = ws->wr1h;
        a.b0 = bl1_0;
        a.C = ws->xm1h; a.M = NMERCH; a.N = HDIM; a.nseg = 2; a.segK = HDIM;
        a.outscale = 1.0f; a.relu = 1; a.out_half = 1;
        gemm_fp16<<<dim3(ceil_div(NMERCH, BM), HDIM / BN), 256, GEMM_SMEM_BYTES, sB>>>(a);
    }
    {
        GemmArgs a = {};
        a.A[0] = ws->xm1h; a.W[0] = ws->wl2h[1];
        a.C = ws->ymh[1]; a.M = NMERCH; a.N = HDIM; a.nseg = 1; a.segK = HDIM;
        a.outscale = 1.0f; a.relu = 0; a.out_half = 1;
        gemm_fp16<<<dim3(ceil_div(NMERCH, BM), HDIM / BN), 256, GEMM_SMEM_BYTES, sB>>>(a);
    }
    cudaEventRecord(evYm1, sB);

    // ======== sC (cont): mu0 -> xu1 -> yu1 -> dual1 ========
    cudaStreamWaitEvent(sC, evCsr, 0);
    cudaStreamWaitEvent(sC, evProj, 0);
    seg_mean_h<<<ceil_div(NUSER * 32, 256), 256, 0, sC>>>(ws->xth[0], 3, ws->muh, NUSER);
    {
        GemmArgs a = {};
        a.A[0] = ws->muh;  a.W[0] = ws->wl3h;
        a.A[1] = ws->xu_h; a.W[1] = ws->wr3h;
        a.b0 = bl3_0;
        a.C = ws->xu1h; a.M = NUSER; a.N = HDIM; a.nseg = 2; a.segK = HDIM;
        a.outscale = 1.0f; a.relu = 1; a.out_half = 1;
        gemm_fp16<<<dim3(ceil_div(NUSER, BM), HDIM / BN), 256, GEMM_SMEM_BYTES, sC>>>(a);
    }
    {
        GemmArgs a = {};
        a.A[0] = ws->xu1h; a.W[0] = ws->wl0h[1];
        a.C = ws->yuh[1]; a.M = NUSER; a.N = HDIM; a.nseg = 1; a.segK = HDIM;
        a.outscale = 1.0f; a.relu = 0; a.out_half = 1;
        gemm_fp16<<<dim3(ceil_div(NUSER, BM), HDIM / BN), 256, GEMM_SMEM_BYTES, sC>>>(a);
    }
    cudaStreamWaitEvent(sC, evYm1, 0);
    seg_mean_dual_h<<<ceil_div(NTX * 32, 256), 256, 0, sC>>>(ws->yuh[1], ws->ymh[1], ws->gts[1]);
    cudaEventRecord(evGts1, sC);

    // ======== s0 (cont): xtL0 -> xtL1 -> fused head ========
    cudaStreamWaitEvent(s0, evGts0, 0);
    {
        GemmArgs a = {};
        a.A[0] = ws->xth[0]; a.W[0] = ws->wsum_h[0];
        a.b0 = bl0_0; a.b1 = bl2_0;
        a.E0 = ws->gts[0];
        a.C = ws->xth[1]; a.M = NTX; a.N = HDIM; a.nseg = 1; a.segK = HDIM;
        a.outscale = 0.5f; a.relu = 1; a.out_half = 1;
        gemm_fp16<<<dim3(ceil_div(NTX, BM), HDIM / BN), 256, GEMM_SMEM_BYTES, s0>>>(a);
    }
    cudaStreamWaitEvent(s0, evGts1, 0);
    {
        GemmArgs a = {};
        a.A[0] = ws->xth[1]; a.W[0] = ws->wsum_h[1];
        a.b0 = bl0_1; a.b1 = bl2_1;
        a.E0 = ws->gts[1];
        a.C = ws->xth[0]; a.M = NTX; a.N = HDIM; a.nseg = 1; a.segK = HDIM;
        a.outscale = 0.5f; a.relu = 1; a.out_half = 1;
        gemm_fp16<<<dim3(ceil_div(NTX, BM), HDIM / BN), 256, GEMM_SMEM_BYTES, s0>>>(a);
    }
    {
        GemmArgs a = {};
        a.A[0] = ws->xth[0]; a.W[0] = ws->wcat_h; a.b0 = ws->bcat;
        a.C = out; a.M = NTX; a.N = HDIM; a.nseg = 1; a.segK = HDIM;
        a.outscale = 1.0f; a.relu = 1;
        a.headmode = 1; a.w2 = ws->w2cat; a.b2c = bc2; a.b2v = bv2;
        gemm_fp16<<<dim3(ceil_div(NTX, BM), HDIM / BN), 256, GEMM_SMEM_BYTES, s0>>>(a);
    }
}